// round 1
// baseline (speedup 1.0000x reference)
#include <cuda_runtime.h>
#include <cuda_bf16.h>
#include <math.h>

// ---------------------------------------------------------------------------
// Problem constants
// ---------------------------------------------------------------------------
#define BATCH    2
#define SEQ      2048
#define DMODEL   2048
#define NHEADS   16
#define NKV      4
#define HDIM     128
#define M_TOK    (BATCH*SEQ)           // 4096

// ---------------------------------------------------------------------------
// Scratch (static device allocations; allowed by harness rules)
// ---------------------------------------------------------------------------
__device__ float g_projq [M_TOK * DMODEL];           // [4096,2048] pre-rope Q
__device__ float g_projkv[M_TOK * (NKV*2*HDIM)];     // [4096,1024] pre-rope KV
__device__ float g_q[BATCH*NHEADS*SEQ*HDIM];         // [B,H,S,D]  rope'd + scaled
__device__ float g_k[BATCH*NKV*SEQ*HDIM];            // [B,KV,S,D] rope'd
__device__ float g_v[BATCH*NKV*SEQ*HDIM];            // [B,KV,S,D]
__device__ float g_x[M_TOK * DMODEL];                // attention out [B,S,H*D]

// ---------------------------------------------------------------------------
// SGEMM: C[M,N] = A[M,K] @ B[K,N] + bias[N]   (row-major, 128x128x16 tiles)
// 256 threads, 8x8 micro-tile per thread, split-column mapping for
// conflict-free LDS.128.
// ---------------------------------------------------------------------------
__global__ __launch_bounds__(256) void sgemm_bias_kernel(
    const float* __restrict__ A, const float* __restrict__ B,
    const float* __restrict__ bias, float* __restrict__ C,
    int M, int N, int K)
{
    __shared__ float As[16][128];   // transposed A tile: As[k][m]
    __shared__ float Bs[16][128];

    const int tid = threadIdx.x;
    const int tx  = tid & 15;
    const int ty  = tid >> 4;
    const int bm  = blockIdx.y * 128;
    const int bn  = blockIdx.x * 128;

    float acc[8][8];
    {
        float b0[4], b1[4];
        #pragma unroll
        for (int j = 0; j < 4; j++) {
            b0[j] = bias[bn + tx*4 + j];
            b1[j] = bias[bn + 64 + tx*4 + j];
        }
        #pragma unroll
        for (int i = 0; i < 8; i++) {
            #pragma unroll
            for (int j = 0; j < 4; j++) { acc[i][j] = b0[j]; acc[i][4+j] = b1[j]; }
        }
    }

    for (int k0 = 0; k0 < K; k0 += 16) {
        // A tile: 128 rows x 16 cols  (512 float4 slots)
        #pragma unroll
        for (int i = 0; i < 2; i++) {
            int slot = tid + i*256;
            int row  = slot >> 2;
            int c    = (slot & 3) * 4;
            float4 v = *(const float4*)(A + (size_t)(bm + row)*K + k0 + c);
            As[c+0][row] = v.x; As[c+1][row] = v.y;
            As[c+2][row] = v.z; As[c+3][row] = v.w;
        }
        // B tile: 16 rows x 128 cols
        #pragma unroll
        for (int i = 0; i < 2; i++) {
            int slot = tid + i*256;
            int row  = slot >> 5;
            int c    = (slot & 31) * 4;
            *(float4*)(&Bs[row][c]) = *(const float4*)(B + (size_t)(k0 + row)*N + bn + c);
        }
        __syncthreads();

        #pragma unroll
        for (int kk = 0; kk < 16; kk++) {
            float a[8], b[8];
            *(float4*)(a)     = *(const float4*)(&As[kk][ty*8]);
            *(float4*)(a + 4) = *(const float4*)(&As[kk][ty*8 + 4]);
            *(float4*)(b)     = *(const float4*)(&Bs[kk][tx*4]);
            *(float4*)(b + 4) = *(const float4*)(&Bs[kk][64 + tx*4]);
            #pragma unroll
            for (int i = 0; i < 8; i++)
                #pragma unroll
                for (int j = 0; j < 8; j++)
                    acc[i][j] += a[i]*b[j];
        }
        __syncthreads();
    }

    #pragma unroll
    for (int i = 0; i < 8; i++) {
        size_t off = (size_t)(bm + ty*8 + i)*N + bn;
        float4 v0 = make_float4(acc[i][0], acc[i][1], acc[i][2], acc[i][3]);
        float4 v1 = make_float4(acc[i][4], acc[i][5], acc[i][6], acc[i][7]);
        *(float4*)(C + off + tx*4)      = v0;
        *(float4*)(C + off + 64 + tx*4) = v1;
    }
}

// ---------------------------------------------------------------------------
// RoPE for Q (also folds in the 1/sqrt(HD) scale), relayout -> [B,H,S,D]
// ---------------------------------------------------------------------------
__global__ void rope_q_kernel(const float* __restrict__ proj,
                              const int* __restrict__ seq_pos,
                              float* __restrict__ Qo)
{
    int idx = blockIdx.x*blockDim.x + threadIdx.x;
    if (idx >= BATCH*SEQ*NHEADS*64) return;
    int i = idx & 63;
    int h = (idx >> 6) & 15;
    int s = (idx >> 10) & 2047;
    int b = idx >> 21;

    float pos  = (float)seq_pos[b*SEQ + s];
    float frac = (float)(2*i) * (1.0f/128.0f);
    float ts   = powf(10000.0f, frac);      // replicate fp32 reference path
    float ang  = pos / ts;
    float sv, cv; sincosf(ang, &sv, &cv);

    const float* src = proj + (size_t)(b*SEQ + s)*DMODEL + h*HDIM;
    float x1 = src[i], x2 = src[i + 64];
    const float scale = 0.08838834764831845f;   // 1/sqrt(128)
    float* dst = Qo + (((size_t)(b*NHEADS + h))*SEQ + s)*HDIM;
    dst[i]      = (x1*cv - x2*sv) * scale;
    dst[i + 64] = (x2*cv + x1*sv) * scale;
}

// ---------------------------------------------------------------------------
// RoPE for K + copy of V, relayout -> [B,KV,S,D]
// ---------------------------------------------------------------------------
__global__ void rope_kv_kernel(const float* __restrict__ proj,
                               const int* __restrict__ seq_pos,
                               float* __restrict__ Ko, float* __restrict__ Vo)
{
    int idx = blockIdx.x*blockDim.x + threadIdx.x;
    if (idx >= BATCH*SEQ*NKV*64) return;
    int i  = idx & 63;
    int kv = (idx >> 6) & 3;
    int s  = (idx >> 8) & 2047;
    int b  = idx >> 19;

    float pos  = (float)seq_pos[b*SEQ + s];
    float frac = (float)(2*i) * (1.0f/128.0f);
    float ts   = powf(10000.0f, frac);
    float ang  = pos / ts;
    float sv, cv; sincosf(ang, &sv, &cv);

    const float* src = proj + (size_t)(b*SEQ + s)*(NKV*2*HDIM) + kv*(2*HDIM);
    float k1 = src[i],       k2 = src[i + 64];
    float v1 = src[128 + i], v2 = src[192 + i];

    size_t base = (((size_t)(b*NKV + kv))*SEQ + s)*HDIM;
    Ko[base + i]      = k1*cv - k2*sv;
    Ko[base + i + 64] = k2*cv + k1*sv;
    Vo[base + i]      = v1;
    Vo[base + i + 64] = v2;
}

// ---------------------------------------------------------------------------
// Flash attention, fp32, causal, GQA (head h uses kv head h/4)
// Block: 256 threads, tile BQ=64 x BK=64, full HD=128.
// Dynamic smem: Qs[64][132] Ks[64][132] Vs[64][128] Ps[64][64]  = 116736 B
// ---------------------------------------------------------------------------
#define QSTRIDE 132

__global__ __launch_bounds__(256) void flash_attn_kernel(
    const float* __restrict__ Q, const float* __restrict__ Kg,
    const float* __restrict__ Vg, float* __restrict__ X)
{
    extern __shared__ float sm[];
    float* Qs = sm;                        // 64 x 132
    float* Ks = Qs + 64*QSTRIDE;           // 64 x 132
    float* Vs = Ks + 64*QSTRIDE;           // 64 x 128
    float* Ps = Vs + 64*128;               // 64 x 64

    const int qt  = 31 - blockIdx.x;       // longest blocks first
    const int h   = blockIdx.y;
    const int b   = blockIdx.z;
    const int kvh = h >> 2;
    const int q0  = qt * 64;

    const int tid = threadIdx.x;
    const int tx  = tid & 15;
    const int ty  = tid >> 4;

    const float* qbase = Q  + ((size_t)(b*NHEADS + h)*SEQ + q0)*HDIM;
    const float* kbase = Kg + (size_t)(b*NKV + kvh)*SEQ*HDIM;
    const float* vbase = Vg + (size_t)(b*NKV + kvh)*SEQ*HDIM;

    // Load Q tile (64x128)
    #pragma unroll
    for (int i = 0; i < 8; i++) {
        int slot = tid + i*256;
        int r = slot >> 5;
        int c = (slot & 31) * 4;
        *(float4*)(Qs + r*QSTRIDE + c) = *(const float4*)(qbase + r*HDIM + c);
    }

    float o[4][8];
    float m[4], l[4];
    #pragma unroll
    for (int i = 0; i < 4; i++) {
        m[i] = -INFINITY; l[i] = 0.f;
        #pragma unroll
        for (int j = 0; j < 8; j++) o[i][j] = 0.f;
    }

    for (int kt = 0; kt <= qt; kt++) {
        __syncthreads();   // previous PV done before overwriting K/V
        const float* kb = kbase + (size_t)kt*64*HDIM;
        const float* vb = vbase + (size_t)kt*64*HDIM;
        #pragma unroll
        for (int i = 0; i < 8; i++) {
            int slot = tid + i*256;
            int r = slot >> 5;
            int c = (slot & 31) * 4;
            *(float4*)(Ks + r*QSTRIDE + c) = *(const float4*)(kb + r*HDIM + c);
            *(float4*)(Vs + r*128 + c)     = *(const float4*)(vb + r*HDIM + c);
        }
        __syncthreads();

        // ---- S = Q K^T : rows ty*4+i, cols 16*j+tx (conflict-free) ----
        float s[4][4];
        #pragma unroll
        for (int i = 0; i < 4; i++)
            #pragma unroll
            for (int j = 0; j < 4; j++) s[i][j] = 0.f;

        #pragma unroll 4
        for (int d = 0; d < HDIM; d += 4) {
            float4 qv[4], kv[4];
            #pragma unroll
            for (int i = 0; i < 4; i++)
                qv[i] = *(const float4*)(Qs + (ty*4 + i)*QSTRIDE + d);
            #pragma unroll
            for (int j = 0; j < 4; j++)
                kv[j] = *(const float4*)(Ks + (16*j + tx)*QSTRIDE + d);
            #pragma unroll
            for (int i = 0; i < 4; i++)
                #pragma unroll
                for (int j = 0; j < 4; j++)
                    s[i][j] += qv[i].x*kv[j].x + qv[i].y*kv[j].y
                             + qv[i].z*kv[j].z + qv[i].w*kv[j].w;
        }

        if (kt == qt) {  // causal mask only on diagonal tile
            #pragma unroll
            for (int i = 0; i < 4; i++) {
                int qi = q0 + ty*4 + i;
                #pragma unroll
                for (int j = 0; j < 4; j++) {
                    int ki = kt*64 + 16*j + tx;
                    if (ki > qi) s[i][j] = -1e30f;
                }
            }
        }

        // ---- online softmax ----
        #pragma unroll
        for (int i = 0; i < 4; i++) {
            float tm = fmaxf(fmaxf(s[i][0], s[i][1]), fmaxf(s[i][2], s[i][3]));
            #pragma unroll
            for (int off = 8; off >= 1; off >>= 1)
                tm = fmaxf(tm, __shfl_xor_sync(0xffffffffu, tm, off));
            float mn   = fmaxf(m[i], tm);
            float corr = __expf(m[i] - mn);
            float tsum = 0.f;
            #pragma unroll
            for (int j = 0; j < 4; j++) {
                float p = __expf(s[i][j] - mn);
                s[i][j] = p;
                tsum += p;
            }
            #pragma unroll
            for (int off = 8; off >= 1; off >>= 1)
                tsum += __shfl_xor_sync(0xffffffffu, tsum, off);
            l[i] = l[i]*corr + tsum;
            m[i] = mn;
            #pragma unroll
            for (int j = 0; j < 8; j++) o[i][j] *= corr;
            #pragma unroll
            for (int j = 0; j < 4; j++)
                Ps[(ty*4 + i)*64 + 16*j + tx] = s[i][j];
        }
        __syncthreads();

        // ---- O += P V : cols tx*4+j and 64+tx*4+j ----
        #pragma unroll 4
        for (int kk = 0; kk < 64; kk++) {
            float4 v0 = *(const float4*)(Vs + kk*128 + tx*4);
            float4 v1 = *(const float4*)(Vs + kk*128 + 64 + tx*4);
            #pragma unroll
            for (int i = 0; i < 4; i++) {
                float p = Ps[(ty*4 + i)*64 + kk];
                o[i][0] += p*v0.x; o[i][1] += p*v0.y;
                o[i][2] += p*v0.z; o[i][3] += p*v0.w;
                o[i][4] += p*v1.x; o[i][5] += p*v1.y;
                o[i][6] += p*v1.z; o[i][7] += p*v1.w;
            }
        }
    }

    // ---- finalize + store to X as [B,S,H,D] ----
    #pragma unroll
    for (int i = 0; i < 4; i++) {
        float inv = 1.f / l[i];
        int row = q0 + ty*4 + i;
        float* dst = X + (((size_t)(b*SEQ + row))*NHEADS + h)*HDIM;
        float4 v0 = make_float4(o[i][0]*inv, o[i][1]*inv, o[i][2]*inv, o[i][3]*inv);
        float4 v1 = make_float4(o[i][4]*inv, o[i][5]*inv, o[i][6]*inv, o[i][7]*inv);
        *(float4*)(dst + tx*4)      = v0;
        *(float4*)(dst + 64 + tx*4) = v1;
    }
}

// ---------------------------------------------------------------------------
// Launch
// ---------------------------------------------------------------------------
extern "C" void kernel_launch(void* const* d_in, const int* in_sizes, int n_in,
                              void* d_out, int out_size)
{
    const float* inputs  = (const float*)d_in[0];
    const int*   seq_pos = (const int*)  d_in[1];
    const float* wq      = (const float*)d_in[2];
    const float* bq      = (const float*)d_in[3];
    const float* wkv     = (const float*)d_in[4];
    const float* bkv     = (const float*)d_in[5];
    const float* wo      = (const float*)d_in[6];
    const float* bo      = (const float*)d_in[7];
    float* out = (float*)d_out;

    float *projq, *projkv, *q, *k, *v, *x;
    cudaGetSymbolAddress((void**)&projq,  g_projq);
    cudaGetSymbolAddress((void**)&projkv, g_projkv);
    cudaGetSymbolAddress((void**)&q,      g_q);
    cudaGetSymbolAddress((void**)&k,      g_k);
    cudaGetSymbolAddress((void**)&v,      g_v);
    cudaGetSymbolAddress((void**)&x,      g_x);

    const int FLASH_SMEM = (64*QSTRIDE*2 + 64*128 + 64*64) * 4;   // 116736 B
    cudaFuncSetAttribute(flash_attn_kernel,
                         cudaFuncAttributeMaxDynamicSharedMemorySize, FLASH_SMEM);

    // 1) Q projection: [4096,2048] x [2048,2048]
    sgemm_bias_kernel<<<dim3(DMODEL/128, M_TOK/128), 256>>>(
        inputs, wq, bq, projq, M_TOK, DMODEL, DMODEL);
    // 2) KV projection: [4096,2048] x [2048,1024]
    sgemm_bias_kernel<<<dim3((NKV*2*HDIM)/128, M_TOK/128), 256>>>(
        inputs, wkv, bkv, projkv, M_TOK, NKV*2*HDIM, DMODEL);
    // 3) RoPE + relayout
    rope_q_kernel<<<(BATCH*SEQ*NHEADS*64)/256, 256>>>(projq, seq_pos, q);
    rope_kv_kernel<<<(BATCH*SEQ*NKV*64)/256, 256>>>(projkv, seq_pos, k, v);
    // 4) Flash attention
    flash_attn_kernel<<<dim3(SEQ/64, NHEADS, BATCH), 256, FLASH_SMEM>>>(q, k, v, x);
    // 5) Output projection: [4096,2048] x [2048,2048] + bo
    sgemm_bias_kernel<<<dim3(DMODEL/128, M_TOK/128), 256>>>(
        x, wo, bo, out, M_TOK, DMODEL, DMODEL);
}

// round 2
// speedup vs baseline: 1.4405x; 1.4405x over previous
#include <cuda_runtime.h>
#include <cuda_bf16.h>
#include <math.h>
#include <stdint.h>

// ---------------------------------------------------------------------------
// Problem constants
// ---------------------------------------------------------------------------
#define BATCH    2
#define SEQ      2048
#define DMODEL   2048
#define NHEADS   16
#define NKV      4
#define HDIM     128
#define M_TOK    (BATCH*SEQ)           // 4096

// ---------------------------------------------------------------------------
// Scratch
// ---------------------------------------------------------------------------
__device__ float g_in_hi [M_TOK*DMODEL];
__device__ float g_in_lo [M_TOK*DMODEL];
__device__ float g_wq_hi [DMODEL*DMODEL];
__device__ float g_wq_lo [DMODEL*DMODEL];
__device__ float g_wkv_hi[DMODEL*NKV*2*HDIM];
__device__ float g_wkv_lo[DMODEL*NKV*2*HDIM];
__device__ float g_wo_hi [DMODEL*DMODEL];
__device__ float g_wo_lo [DMODEL*DMODEL];
__device__ float g_projq [M_TOK*DMODEL];
__device__ float g_projkv[M_TOK*NKV*2*HDIM];
__device__ float g_q[BATCH*NHEADS*SEQ*HDIM];
__device__ float g_k[BATCH*NKV*SEQ*HDIM];
__device__ float g_v[BATCH*NKV*SEQ*HDIM];
__device__ float g_x_hi[M_TOK*DMODEL];
__device__ float g_x_lo[M_TOK*DMODEL];

// ---------------------------------------------------------------------------
// Helpers
// ---------------------------------------------------------------------------
__device__ __forceinline__ float tf32_rna(float x) {
    uint32_t u;
    asm("cvt.rna.tf32.f32 %0, %1;" : "=r"(u) : "f"(x));
    return __uint_as_float(u);
}
__device__ __forceinline__ uint32_t fu(float x) { return __float_as_uint(x); }

__device__ __forceinline__ void mma_tf32(float c[4], const uint32_t a[4], const uint32_t b[2]) {
    asm volatile(
        "mma.sync.aligned.m16n8k8.row.col.f32.tf32.tf32.f32 "
        "{%0,%1,%2,%3},{%4,%5,%6,%7},{%8,%9},{%0,%1,%2,%3};"
        : "+f"(c[0]), "+f"(c[1]), "+f"(c[2]), "+f"(c[3])
        : "r"(a[0]), "r"(a[1]), "r"(a[2]), "r"(a[3]), "r"(b[0]), "r"(b[1]));
}

__device__ __forceinline__ void cpa16(float* smem, const float* g) {
    uint32_t s = (uint32_t)__cvta_generic_to_shared(smem);
    asm volatile("cp.async.cg.shared.global [%0], [%1], 16;\n" :: "r"(s), "l"(g));
}
__device__ __forceinline__ void cp_commit() { asm volatile("cp.async.commit_group;"); }
__device__ __forceinline__ void cp_wait1()  { asm volatile("cp.async.wait_group 1;"); }
__device__ __forceinline__ void cp_wait0()  { asm volatile("cp.async.wait_group 0;"); }

// ---------------------------------------------------------------------------
// Split fp32 -> (tf32 hi, tf32 lo), vectorized
// ---------------------------------------------------------------------------
__global__ void round_split4(const float4* __restrict__ src,
                             float4* __restrict__ hi, float4* __restrict__ lo, int n4)
{
    int i = blockIdx.x*blockDim.x + threadIdx.x;
    if (i >= n4) return;
    float4 x = src[i], h, l;
    h.x = tf32_rna(x.x); l.x = tf32_rna(x.x - h.x);
    h.y = tf32_rna(x.y); l.y = tf32_rna(x.y - h.y);
    h.z = tf32_rna(x.z); l.z = tf32_rna(x.z - h.z);
    h.w = tf32_rna(x.w); l.w = tf32_rna(x.w - h.w);
    hi[i] = h; lo[i] = l;
}

// ---------------------------------------------------------------------------
// 3xTF32 GEMM: C[M,N] = (Ah+Al)@(Bh+Bl) + bias    (error ~ fp32)
// 128x128x32 tiles, 256 threads, 8 warps = 2(M) x 4(N), warp tile 64x32.
// cp.async double-buffered.
// ---------------------------------------------------------------------------
#define GA_STR 36
#define GB_STR 132
#define GBUF   17664   // floats per buffer: 2*(128*36) + 2*(32*132)

__global__ __launch_bounds__(256, 1) void gemm3_tf32(
    const float* __restrict__ Ah, const float* __restrict__ Al,
    const float* __restrict__ Bh, const float* __restrict__ Bl,
    const float* __restrict__ bias, float* __restrict__ C,
    int M, int N, int K)
{
    extern __shared__ float sm[];
    const int tid  = threadIdx.x;
    const int lane = tid & 31, wid = tid >> 5;
    const int wr   = wid >> 2, wc = wid & 3;     // 2 x 4 warp grid
    const int gr   = lane >> 2, qd = lane & 3;
    const int bm   = blockIdx.y * 128;
    const int bn   = blockIdx.x * 128;

    float acc[4][4][4];
    #pragma unroll
    for (int i = 0; i < 4; i++)
        #pragma unroll
        for (int j = 0; j < 4; j++)
            #pragma unroll
            for (int r = 0; r < 4; r++) acc[i][j][r] = 0.f;

    auto load_tile = [&](int buf, int k0) {
        float* sAh = sm + buf*GBUF;
        float* sAl = sAh + 4608;
        float* sBh = sm + buf*GBUF + 9216;
        float* sBl = sBh + 4224;
        #pragma unroll
        for (int i = 0; i < 4; i++) {               // A: 128 x 32
            int slot = tid + i*256;
            int r = slot >> 3, c = (slot & 7)*4;
            size_t go = (size_t)(bm + r)*K + k0 + c;
            cpa16(sAh + r*GA_STR + c, Ah + go);
            cpa16(sAl + r*GA_STR + c, Al + go);
        }
        #pragma unroll
        for (int i = 0; i < 4; i++) {               // B: 32 x 128
            int slot = tid + i*256;
            int r = slot >> 5, c = (slot & 31)*4;
            size_t go = (size_t)(k0 + r)*N + bn + c;
            cpa16(sBh + r*GB_STR + c, Bh + go);
            cpa16(sBl + r*GB_STR + c, Bl + go);
        }
    };

    load_tile(0, 0);
    cp_commit();

    const int KT = K / 32;
    int buf = 0;
    for (int it = 0; it < KT; it++) {
        if (it + 1 < KT) { load_tile(buf ^ 1, (it + 1)*32); cp_commit(); cp_wait1(); }
        else             { cp_wait0(); }
        __syncthreads();

        const float* sAh = sm + buf*GBUF;
        const float* sAl = sAh + 4608;
        const float* sBh = sm + buf*GBUF + 9216;
        const float* sBl = sBh + 4224;

        #pragma unroll
        for (int ks = 0; ks < 4; ks++) {
            const int k = ks*8;
            uint32_t ah[4][4], al[4][4], bh[4][2], bl[4][2];
            const int ra = wr*64 + gr;
            #pragma unroll
            for (int mt = 0; mt < 4; mt++) {
                int r = ra + mt*16;
                ah[mt][0] = fu(sAh[(r  )*GA_STR + k     + qd]);
                ah[mt][1] = fu(sAh[(r+8)*GA_STR + k     + qd]);
                ah[mt][2] = fu(sAh[(r  )*GA_STR + k + 4 + qd]);
                ah[mt][3] = fu(sAh[(r+8)*GA_STR + k + 4 + qd]);
                al[mt][0] = fu(sAl[(r  )*GA_STR + k     + qd]);
                al[mt][1] = fu(sAl[(r+8)*GA_STR + k     + qd]);
                al[mt][2] = fu(sAl[(r  )*GA_STR + k + 4 + qd]);
                al[mt][3] = fu(sAl[(r+8)*GA_STR + k + 4 + qd]);
            }
            const int cb = wc*32 + gr;
            #pragma unroll
            for (int nt = 0; nt < 4; nt++) {
                int c = cb + nt*8;
                bh[nt][0] = fu(sBh[(k     + qd)*GB_STR + c]);
                bh[nt][1] = fu(sBh[(k + 4 + qd)*GB_STR + c]);
                bl[nt][0] = fu(sBl[(k     + qd)*GB_STR + c]);
                bl[nt][1] = fu(sBl[(k + 4 + qd)*GB_STR + c]);
            }
            #pragma unroll
            for (int mt = 0; mt < 4; mt++)
                #pragma unroll
                for (int nt = 0; nt < 4; nt++) {
                    mma_tf32(acc[mt][nt], ah[mt], bh[nt]);
                    mma_tf32(acc[mt][nt], al[mt], bh[nt]);
                    mma_tf32(acc[mt][nt], ah[mt], bl[nt]);
                }
        }
        __syncthreads();
        buf ^= 1;
    }

    // epilogue: + bias, store
    #pragma unroll
    for (int nt = 0; nt < 4; nt++) {
        int col = bn + wc*32 + nt*8 + 2*qd;
        float2 bv = *(const float2*)(bias + col);
        #pragma unroll
        for (int mt = 0; mt < 4; mt++) {
            int row = bm + wr*64 + mt*16 + gr;
            *(float2*)(C + (size_t)row*N + col) =
                make_float2(acc[mt][nt][0] + bv.x, acc[mt][nt][1] + bv.y);
            *(float2*)(C + (size_t)(row + 8)*N + col) =
                make_float2(acc[mt][nt][2] + bv.x, acc[mt][nt][3] + bv.y);
        }
    }
}

// ---------------------------------------------------------------------------
// RoPE Q (folds 1/sqrt(HD), tf32-rounds output), -> [B,H,S,D]
// ---------------------------------------------------------------------------
__global__ void rope_q_kernel(const float* __restrict__ proj,
                              const int* __restrict__ seq_pos,
                              float* __restrict__ Qo)
{
    int idx = blockIdx.x*blockDim.x + threadIdx.x;
    if (idx >= BATCH*SEQ*NHEADS*64) return;
    int i = idx & 63;
    int h = (idx >> 6) & 15;
    int s = (idx >> 10) & 2047;
    int b = idx >> 21;

    float pos  = (float)seq_pos[b*SEQ + s];
    float frac = (float)(2*i) * (1.0f/128.0f);
    float ts   = powf(10000.0f, frac);
    float ang  = pos / ts;
    float sv, cv; sincosf(ang, &sv, &cv);

    const float* src = proj + (size_t)(b*SEQ + s)*DMODEL + h*HDIM;
    float x1 = src[i], x2 = src[i + 64];
    const float scale = 0.08838834764831845f;    // 1/sqrt(128)
    float* dst = Qo + (((size_t)(b*NHEADS + h))*SEQ + s)*HDIM;
    dst[i]      = tf32_rna((x1*cv - x2*sv) * scale);
    dst[i + 64] = tf32_rna((x2*cv + x1*sv) * scale);
}

// ---------------------------------------------------------------------------
// RoPE K + copy V (tf32-rounded), -> [B,KV,S,D]
// ---------------------------------------------------------------------------
__global__ void rope_kv_kernel(const float* __restrict__ proj,
                               const int* __restrict__ seq_pos,
                               float* __restrict__ Ko, float* __restrict__ Vo)
{
    int idx = blockIdx.x*blockDim.x + threadIdx.x;
    if (idx >= BATCH*SEQ*NKV*64) return;
    int i  = idx & 63;
    int kv = (idx >> 6) & 3;
    int s  = (idx >> 8) & 2047;
    int b  = idx >> 19;

    float pos  = (float)seq_pos[b*SEQ + s];
    float frac = (float)(2*i) * (1.0f/128.0f);
    float ts   = powf(10000.0f, frac);
    float ang  = pos / ts;
    float sv, cv; sincosf(ang, &sv, &cv);

    const float* src = proj + (size_t)(b*SEQ + s)*(NKV*2*HDIM) + kv*(2*HDIM);
    float k1 = src[i],       k2 = src[i + 64];
    float v1 = src[128 + i], v2 = src[192 + i];

    size_t base = (((size_t)(b*NKV + kv))*SEQ + s)*HDIM;
    Ko[base + i]      = tf32_rna(k1*cv - k2*sv);
    Ko[base + i + 64] = tf32_rna(k2*cv + k1*sv);
    Vo[base + i]      = tf32_rna(v1);
    Vo[base + i + 64] = tf32_rna(v2);
}

// ---------------------------------------------------------------------------
// Flash attention with tf32 mma, causal, GQA. 256 thr = 8 warps.
// Warp (wr, wc): wr = wid>>1 owns rows [wr*16, +16); wc = wid&1.
//   QK: warp computes S[16][32] at col-half wc (4 ntiles)
//   PV: warp computes O[16][64] at col-half wc (8 ntiles)
// Output written as tf32 hi/lo split (feeds 3xTF32 O-projection).
// ---------------------------------------------------------------------------
#define FQ_STR 132
#define FP_STR 76

__global__ __launch_bounds__(256, 1) void flash_tf32(
    const float* __restrict__ Q, const float* __restrict__ Kg,
    const float* __restrict__ Vg,
    float* __restrict__ Xh, float* __restrict__ Xl)
{
    extern __shared__ float sm[];
    float* Qs   = sm;                 // 64 x 132
    float* Ks   = Qs + 64*FQ_STR;     // 64 x 132
    float* Vs   = Ks + 64*FQ_STR;     // 64 x 132
    float* Ps   = Vs + 64*FQ_STR;     // 64 x 76
    float* redm = Ps + 64*FP_STR;     // 128
    float* reds = redm + 128;         // 128

    const int qt  = 31 - blockIdx.x;
    const int h   = blockIdx.y;
    const int b   = blockIdx.z;
    const int kvh = h >> 2;
    const int q0  = qt * 64;

    const int tid  = threadIdx.x;
    const int lane = tid & 31, wid = tid >> 5;
    const int wr   = wid >> 1, wc = wid & 1;
    const int gr   = lane >> 2, qd = lane & 3;
    const int r0   = wr*16 + gr, r1 = r0 + 8;

    const float* qb = Q  + ((size_t)(b*NHEADS + h)*SEQ + q0)*HDIM;
    const float* kb = Kg + (size_t)(b*NKV + kvh)*SEQ*HDIM;
    const float* vb = Vg + (size_t)(b*NKV + kvh)*SEQ*HDIM;

    #pragma unroll
    for (int i = 0; i < 8; i++) {
        int slot = tid + i*256;
        int r = slot >> 5, c = (slot & 31)*4;
        *(float4*)(Qs + r*FQ_STR + c) = *(const float4*)(qb + r*HDIM + c);
    }

    float o[8][4];
    #pragma unroll
    for (int i = 0; i < 8; i++)
        #pragma unroll
        for (int j = 0; j < 4; j++) o[i][j] = 0.f;
    float m0 = -INFINITY, m1 = -INFINITY, l0 = 0.f, l1 = 0.f;

    for (int kt = 0; kt <= qt; kt++) {
        __syncthreads();
        const float* kp = kb + (size_t)kt*64*HDIM;
        const float* vp = vb + (size_t)kt*64*HDIM;
        #pragma unroll
        for (int i = 0; i < 8; i++) {
            int slot = tid + i*256;
            int r = slot >> 5, c = (slot & 31)*4;
            *(float4*)(Ks + r*FQ_STR + c) = *(const float4*)(kp + r*HDIM + c);
            *(float4*)(Vs + r*FQ_STR + c) = *(const float4*)(vp + r*HDIM + c);
        }
        __syncthreads();

        // ---- S = Q K^T via mma ----
        float s[4][4];
        #pragma unroll
        for (int nt = 0; nt < 4; nt++)
            #pragma unroll
            for (int j = 0; j < 4; j++) s[nt][j] = 0.f;

        #pragma unroll
        for (int ks = 0; ks < 16; ks++) {
            const int k = ks*8;
            uint32_t a[4];
            a[0] = fu(Qs[r0*FQ_STR + k     + qd]);
            a[1] = fu(Qs[r1*FQ_STR + k     + qd]);
            a[2] = fu(Qs[r0*FQ_STR + k + 4 + qd]);
            a[3] = fu(Qs[r1*FQ_STR + k + 4 + qd]);
            #pragma unroll
            for (int nt = 0; nt < 4; nt++) {
                int cn = wc*32 + nt*8 + gr;
                uint32_t bf[2];
                bf[0] = fu(Ks[cn*FQ_STR + k     + qd]);
                bf[1] = fu(Ks[cn*FQ_STR + k + 4 + qd]);
                mma_tf32(s[nt], a, bf);
            }
        }

        if (kt == qt) {
            #pragma unroll
            for (int nt = 0; nt < 4; nt++) {
                int cg = kt*64 + wc*32 + nt*8 + 2*qd;
                if (cg     > q0 + r0) s[nt][0] = -1e30f;
                if (cg + 1 > q0 + r0) s[nt][1] = -1e30f;
                if (cg     > q0 + r1) s[nt][2] = -1e30f;
                if (cg + 1 > q0 + r1) s[nt][3] = -1e30f;
            }
        }

        // ---- row max (quad reduce + cross-warp exchange) ----
        float mx0 = -INFINITY, mx1 = -INFINITY;
        #pragma unroll
        for (int nt = 0; nt < 4; nt++) {
            mx0 = fmaxf(mx0, fmaxf(s[nt][0], s[nt][1]));
            mx1 = fmaxf(mx1, fmaxf(s[nt][2], s[nt][3]));
        }
        mx0 = fmaxf(mx0, __shfl_xor_sync(0xffffffffu, mx0, 1));
        mx0 = fmaxf(mx0, __shfl_xor_sync(0xffffffffu, mx0, 2));
        mx1 = fmaxf(mx1, __shfl_xor_sync(0xffffffffu, mx1, 1));
        mx1 = fmaxf(mx1, __shfl_xor_sync(0xffffffffu, mx1, 2));
        if (qd == 0) { redm[wc*64 + r0] = mx0; redm[wc*64 + r1] = mx1; }
        __syncthreads();
        float nm0 = fmaxf(m0, fmaxf(mx0, redm[(wc ^ 1)*64 + r0]));
        float nm1 = fmaxf(m1, fmaxf(mx1, redm[(wc ^ 1)*64 + r1]));
        float corr0 = __expf(m0 - nm0), corr1 = __expf(m1 - nm1);

        // ---- exp, write P (tf32-rounded), row sums ----
        float sum0 = 0.f, sum1 = 0.f;
        #pragma unroll
        for (int nt = 0; nt < 4; nt++) {
            float p0 = tf32_rna(__expf(s[nt][0] - nm0));
            float p1 = tf32_rna(__expf(s[nt][1] - nm0));
            float p2 = tf32_rna(__expf(s[nt][2] - nm1));
            float p3 = tf32_rna(__expf(s[nt][3] - nm1));
            sum0 += p0 + p1; sum1 += p2 + p3;
            int cc = wc*32 + nt*8 + 2*qd;
            *(float2*)(Ps + r0*FP_STR + cc) = make_float2(p0, p1);
            *(float2*)(Ps + r1*FP_STR + cc) = make_float2(p2, p3);
        }
        sum0 += __shfl_xor_sync(0xffffffffu, sum0, 1);
        sum0 += __shfl_xor_sync(0xffffffffu, sum0, 2);
        sum1 += __shfl_xor_sync(0xffffffffu, sum1, 1);
        sum1 += __shfl_xor_sync(0xffffffffu, sum1, 2);
        if (qd == 0) { reds[wc*64 + r0] = sum0; reds[wc*64 + r1] = sum1; }
        __syncthreads();
        l0 = l0*corr0 + sum0 + reds[(wc ^ 1)*64 + r0];
        l1 = l1*corr1 + sum1 + reds[(wc ^ 1)*64 + r1];
        m0 = nm0; m1 = nm1;

        #pragma unroll
        for (int nt = 0; nt < 8; nt++) {
            o[nt][0] *= corr0; o[nt][1] *= corr0;
            o[nt][2] *= corr1; o[nt][3] *= corr1;
        }

        // ---- O += P V via mma ----
        #pragma unroll
        for (int ks = 0; ks < 8; ks++) {
            const int k = ks*8;
            uint32_t a[4];
            a[0] = fu(Ps[r0*FP_STR + k     + qd]);
            a[1] = fu(Ps[r1*FP_STR + k     + qd]);
            a[2] = fu(Ps[r0*FP_STR + k + 4 + qd]);
            a[3] = fu(Ps[r1*FP_STR + k + 4 + qd]);
            #pragma unroll
            for (int nt = 0; nt < 8; nt++) {
                int cn = wc*64 + nt*8 + gr;
                uint32_t bf[2];
                bf[0] = fu(Vs[(k     + qd)*FQ_STR + cn]);
                bf[1] = fu(Vs[(k + 4 + qd)*FQ_STR + cn]);
                mma_tf32(o[nt], a, bf);
            }
        }
    }

    // ---- finalize: normalize, split hi/lo, store [B,S,H*D] ----
    float inv0 = 1.f / l0, inv1 = 1.f / l1;
    size_t rb0 = ((size_t)(b*SEQ + q0 + r0))*DMODEL + h*HDIM;
    size_t rb1 = ((size_t)(b*SEQ + q0 + r1))*DMODEL + h*HDIM;
    #pragma unroll
    for (int nt = 0; nt < 8; nt++) {
        int cc = wc*64 + nt*8 + 2*qd;
        float v0 = o[nt][0]*inv0, v1 = o[nt][1]*inv0;
        float v2 = o[nt][2]*inv1, v3 = o[nt][3]*inv1;
        float h0 = tf32_rna(v0), h1 = tf32_rna(v1);
        float h2 = tf32_rna(v2), h3 = tf32_rna(v3);
        *(float2*)(Xh + rb0 + cc) = make_float2(h0, h1);
        *(float2*)(Xl + rb0 + cc) = make_float2(tf32_rna(v0 - h0), tf32_rna(v1 - h1));
        *(float2*)(Xh + rb1 + cc) = make_float2(h2, h3);
        *(float2*)(Xl + rb1 + cc) = make_float2(tf32_rna(v2 - h2), tf32_rna(v3 - h3));
    }
}

// ---------------------------------------------------------------------------
// Launch
// ---------------------------------------------------------------------------
extern "C" void kernel_launch(void* const* d_in, const int* in_sizes, int n_in,
                              void* d_out, int out_size)
{
    const float* inputs  = (const float*)d_in[0];
    const int*   seq_pos = (const int*)  d_in[1];
    const float* wq      = (const float*)d_in[2];
    const float* bq      = (const float*)d_in[3];
    const float* wkv     = (const float*)d_in[4];
    const float* bkv     = (const float*)d_in[5];
    const float* wo      = (const float*)d_in[6];
    const float* bo      = (const float*)d_in[7];
    float* out = (float*)d_out;

    float *in_hi, *in_lo, *wq_hi, *wq_lo, *wkv_hi, *wkv_lo, *wo_hi, *wo_lo;
    float *projq, *projkv, *q, *k, *v, *x_hi, *x_lo;
    cudaGetSymbolAddress((void**)&in_hi,  g_in_hi);
    cudaGetSymbolAddress((void**)&in_lo,  g_in_lo);
    cudaGetSymbolAddress((void**)&wq_hi,  g_wq_hi);
    cudaGetSymbolAddress((void**)&wq_lo,  g_wq_lo);
    cudaGetSymbolAddress((void**)&wkv_hi, g_wkv_hi);
    cudaGetSymbolAddress((void**)&wkv_lo, g_wkv_lo);
    cudaGetSymbolAddress((void**)&wo_hi,  g_wo_hi);
    cudaGetSymbolAddress((void**)&wo_lo,  g_wo_lo);
    cudaGetSymbolAddress((void**)&projq,  g_projq);
    cudaGetSymbolAddress((void**)&projkv, g_projkv);
    cudaGetSymbolAddress((void**)&q,      g_q);
    cudaGetSymbolAddress((void**)&k,      g_k);
    cudaGetSymbolAddress((void**)&v,      g_v);
    cudaGetSymbolAddress((void**)&x_hi,   g_x_hi);
    cudaGetSymbolAddress((void**)&x_lo,   g_x_lo);

    const int GEMM_SMEM  = 2*GBUF*4;                                     // 141312
    const int FLASH_SMEM = (3*64*FQ_STR + 64*FP_STR + 256)*4;            // ~121 KB
    cudaFuncSetAttribute(gemm3_tf32,
                         cudaFuncAttributeMaxDynamicSharedMemorySize, GEMM_SMEM);
    cudaFuncSetAttribute(flash_tf32,
                         cudaFuncAttributeMaxDynamicSharedMemorySize, FLASH_SMEM);

    // 0) split operands into tf32 hi/lo
    round_split4<<<(M_TOK*DMODEL/4)/256, 256>>>((const float4*)inputs,
        (float4*)in_hi, (float4*)in_lo, M_TOK*DMODEL/4);
    round_split4<<<(DMODEL*DMODEL/4)/256, 256>>>((const float4*)wq,
        (float4*)wq_hi, (float4*)wq_lo, DMODEL*DMODEL/4);
    round_split4<<<(DMODEL*NKV*2*HDIM/4)/256, 256>>>((const float4*)wkv,
        (float4*)wkv_hi, (float4*)wkv_lo, DMODEL*NKV*2*HDIM/4);
    round_split4<<<(DMODEL*DMODEL/4)/256, 256>>>((const float4*)wo,
        (float4*)wo_hi, (float4*)wo_lo, DMODEL*DMODEL/4);

    // 1) projections (3xTF32)
    gemm3_tf32<<<dim3(DMODEL/128, M_TOK/128), 256, GEMM_SMEM>>>(
        in_hi, in_lo, wq_hi, wq_lo, bq, projq, M_TOK, DMODEL, DMODEL);
    gemm3_tf32<<<dim3((NKV*2*HDIM)/128, M_TOK/128), 256, GEMM_SMEM>>>(
        in_hi, in_lo, wkv_hi, wkv_lo, bkv, projkv, M_TOK, NKV*2*HDIM, DMODEL);

    // 2) RoPE + relayout (tf32-rounded outputs)
    rope_q_kernel<<<(BATCH*SEQ*NHEADS*64)/256, 256>>>(projq, seq_pos, q);
    rope_kv_kernel<<<(BATCH*SEQ*NKV*64)/256, 256>>>(projkv, seq_pos, k, v);

    // 3) flash attention (tf32 mma)
    flash_tf32<<<dim3(SEQ/64, NHEADS, BATCH), 256, FLASH_SMEM>>>(q, k, v, x_hi, x_lo);

    // 4) output projection (3xTF32)
    gemm3_tf32<<<dim3(DMODEL/128, M_TOK/128), 256, GEMM_SMEM>>>(
        x_hi, x_lo, wo_hi, wo_lo, bo, out, M_TOK, DMODEL, DMODEL);
}

// round 4
// speedup vs baseline: 3.6765x; 2.5523x over previous
#include <cuda_runtime.h>
#include <cuda_fp16.h>
#include <math.h>
#include <stdint.h>

// ---------------------------------------------------------------------------
// Problem constants
// ---------------------------------------------------------------------------
#define BATCH    2
#define SEQ      2048
#define DMODEL   2048
#define NHEADS   16
#define NKV      4
#define HDIM     128
#define M_TOK    (BATCH*SEQ)           // 4096
#define KVDIM    (NKV*2*HDIM)          // 1024

// ---------------------------------------------------------------------------
// Scratch
// ---------------------------------------------------------------------------
__device__ __half g_in_h [M_TOK*DMODEL];
__device__ __half g_wq_h [DMODEL*DMODEL];    // transposed [N,K]
__device__ __half g_wkv_h[KVDIM*DMODEL];     // transposed [N,K]
__device__ __half g_wo_h [DMODEL*DMODEL];    // transposed [N,K]
__device__ __half g_x_h  [M_TOK*DMODEL];     // attention out, fp16
__device__ float g_projq [M_TOK*DMODEL];
__device__ float g_projkv[M_TOK*KVDIM];
__device__ float g_q[BATCH*NHEADS*SEQ*HDIM];
__device__ float g_k[BATCH*NKV*SEQ*HDIM];
__device__ float g_v[BATCH*NKV*SEQ*HDIM];

// ---------------------------------------------------------------------------
// Helpers
// ---------------------------------------------------------------------------
__device__ __forceinline__ float tf32_rna(float x) {
    uint32_t u; asm("cvt.rna.tf32.f32 %0, %1;" : "=r"(u) : "f"(x));
    return __uint_as_float(u);
}
__device__ __forceinline__ uint32_t fu(float x) { return __float_as_uint(x); }

__device__ __forceinline__ void mma_tf32(float c[4], const uint32_t a[4], const uint32_t b[2]) {
    asm volatile(
        "mma.sync.aligned.m16n8k8.row.col.f32.tf32.tf32.f32 "
        "{%0,%1,%2,%3},{%4,%5,%6,%7},{%8,%9},{%0,%1,%2,%3};"
        : "+f"(c[0]), "+f"(c[1]), "+f"(c[2]), "+f"(c[3])
        : "r"(a[0]), "r"(a[1]), "r"(a[2]), "r"(a[3]), "r"(b[0]), "r"(b[1]));
}
__device__ __forceinline__ void mma_f16(float c[4], const uint32_t a[4], const uint32_t b[2]) {
    asm volatile(
        "mma.sync.aligned.m16n8k16.row.col.f32.f16.f16.f32 "
        "{%0,%1,%2,%3},{%4,%5,%6,%7},{%8,%9},{%0,%1,%2,%3};"
        : "+f"(c[0]), "+f"(c[1]), "+f"(c[2]), "+f"(c[3])
        : "r"(a[0]), "r"(a[1]), "r"(a[2]), "r"(a[3]), "r"(b[0]), "r"(b[1]));
}

__device__ __forceinline__ void cpa16(void* smem, const void* g) {
    uint32_t s = (uint32_t)__cvta_generic_to_shared(smem);
    asm volatile("cp.async.cg.shared.global [%0], [%1], 16;\n" :: "r"(s), "l"(g));
}
__device__ __forceinline__ void cp_commit() { asm volatile("cp.async.commit_group;"); }
__device__ __forceinline__ void cp_wait1()  { asm volatile("cp.async.wait_group 1;"); }
__device__ __forceinline__ void cp_wait0()  { asm volatile("cp.async.wait_group 0;"); }

// ---------------------------------------------------------------------------
// Staging: fp32 -> fp16 (same layout)
// ---------------------------------------------------------------------------
__global__ void cvt_f16(const float4* __restrict__ src, __half2* __restrict__ dst, int n4)
{
    int i = blockIdx.x*blockDim.x + threadIdx.x;
    if (i >= n4) return;
    float4 x = src[i];
    dst[2*i]   = __floats2half2_rn(x.x, x.y);
    dst[2*i+1] = __floats2half2_rn(x.z, x.w);
}

// ---------------------------------------------------------------------------
// Staging: W[K,N] fp32 -> transposed fp16 [N,K]
// ---------------------------------------------------------------------------
__global__ void tcvt_f16(const float* __restrict__ W, __half* __restrict__ T, int K, int N)
{
    __shared__ float t[32][33];
    int n0 = blockIdx.x*32, k0 = blockIdx.y*32;
    int tx = threadIdx.x, ty = threadIdx.y;  // 32 x 8
    #pragma unroll
    for (int i = 0; i < 4; i++)
        t[ty + 8*i][tx] = W[(size_t)(k0 + ty + 8*i)*N + n0 + tx];
    __syncthreads();
    #pragma unroll
    for (int i = 0; i < 4; i++)
        T[(size_t)(n0 + ty + 8*i)*K + k0 + tx] = __float2half_rn(t[tx][ty + 8*i]);
}

// ---------------------------------------------------------------------------
// fp16 GEMM (fp32 accum): C[M,N] = A[M,K] @ B[N,K]^T + bias
// CTA tile 128x128, BK=64, 256 threads = 8 warps (2x4), warp tile 64x32.
// cp.async double-buffered. m16n8k16 HMMA.
// ---------------------------------------------------------------------------
#define HSTR 72            // half stride per row (64 + 8 pad)
#define HBUF 18432         // halves per buffer: 2 * 128*72

__global__ __launch_bounds__(256) void gemm_f16(
    const __half* __restrict__ A, const __half* __restrict__ B,
    const float* __restrict__ bias, float* __restrict__ C,
    int M, int N, int K)
{
    extern __shared__ __half sh[];
    const int tid  = threadIdx.x;
    const int lane = tid & 31, wid = tid >> 5;
    const int wr   = wid >> 2, wc = wid & 3;
    const int gr   = lane >> 2, qd = lane & 3;
    const int bm   = blockIdx.y*128, bn = blockIdx.x*128;

    float acc[4][4][4];
    #pragma unroll
    for (int i = 0; i < 4; i++)
        #pragma unroll
        for (int j = 0; j < 4; j++)
            #pragma unroll
            for (int r = 0; r < 4; r++) acc[i][j][r] = 0.f;

    auto load_tile = [&](int buf, int k0) {
        __half* sA = sh + buf*HBUF;
        __half* sB = sA + 128*HSTR;
        #pragma unroll
        for (int i = 0; i < 4; i++) {
            int slot = tid + i*256;
            int r = slot >> 3, c8 = (slot & 7)*8;
            cpa16(sA + r*HSTR + c8, A + (size_t)(bm + r)*K + k0 + c8);
            cpa16(sB + r*HSTR + c8, B + (size_t)(bn + r)*K + k0 + c8);
        }
        cp_commit();
    };

    load_tile(0, 0);

    const int KT = K / 64;
    int buf = 0;
    for (int it = 0; it < KT; it++) {
        if (it + 1 < KT) { load_tile(buf ^ 1, (it + 1)*64); cp_wait1(); }
        else             { cp_wait0(); }
        __syncthreads();

        const __half* sA = sh + buf*HBUF;
        const __half* sB = sA + 128*HSTR;

        #pragma unroll
        for (int ks = 0; ks < 4; ks++) {
            const int k = ks*16;
            uint32_t a[4][4], b[4][2];
            #pragma unroll
            for (int mt = 0; mt < 4; mt++) {
                int r = wr*64 + mt*16 + gr;
                a[mt][0] = *(const uint32_t*)(sA + (r  )*HSTR + k     + 2*qd);
                a[mt][1] = *(const uint32_t*)(sA + (r+8)*HSTR + k     + 2*qd);
                a[mt][2] = *(const uint32_t*)(sA + (r  )*HSTR + k + 8 + 2*qd);
                a[mt][3] = *(const uint32_t*)(sA + (r+8)*HSTR + k + 8 + 2*qd);
            }
            #pragma unroll
            for (int nt = 0; nt < 4; nt++) {
                int n = wc*32 + nt*8 + gr;
                b[nt][0] = *(const uint32_t*)(sB + n*HSTR + k     + 2*qd);
                b[nt][1] = *(const uint32_t*)(sB + n*HSTR + k + 8 + 2*qd);
            }
            #pragma unroll
            for (int mt = 0; mt < 4; mt++)
                #pragma unroll
                for (int nt = 0; nt < 4; nt++)
                    mma_f16(acc[mt][nt], a[mt], b[nt]);
        }
        __syncthreads();
        buf ^= 1;
    }

    // epilogue: + bias, fp32 store
    #pragma unroll
    for (int nt = 0; nt < 4; nt++) {
        int col = bn + wc*32 + nt*8 + 2*qd;
        float2 bv = *(const float2*)(bias + col);
        #pragma unroll
        for (int mt = 0; mt < 4; mt++) {
            int row = bm + wr*64 + mt*16 + gr;
            *(float2*)(C + (size_t)row*N + col) =
                make_float2(acc[mt][nt][0] + bv.x, acc[mt][nt][1] + bv.y);
            *(float2*)(C + (size_t)(row + 8)*N + col) =
                make_float2(acc[mt][nt][2] + bv.x, acc[mt][nt][3] + bv.y);
        }
    }
}

// ---------------------------------------------------------------------------
// RoPE Q (folds 1/sqrt(HD), tf32-rounds output), -> [B,H,S,D]
// ---------------------------------------------------------------------------
__global__ void rope_q_kernel(const float* __restrict__ proj,
                              const int* __restrict__ seq_pos,
                              float* __restrict__ Qo)
{
    int idx = blockIdx.x*blockDim.x + threadIdx.x;
    if (idx >= BATCH*SEQ*NHEADS*64) return;
    int i = idx & 63;
    int h = (idx >> 6) & 15;
    int s = (idx >> 10) & 2047;
    int b = idx >> 21;

    float pos  = (float)seq_pos[b*SEQ + s];
    float frac = (float)(2*i) * (1.0f/128.0f);
    float ts   = powf(10000.0f, frac);
    float ang  = pos / ts;
    float sv, cv; sincosf(ang, &sv, &cv);

    const float* src = proj + (size_t)(b*SEQ + s)*DMODEL + h*HDIM;
    float x1 = src[i], x2 = src[i + 64];
    const float scale = 0.08838834764831845f;
    float* dst = Qo + (((size_t)(b*NHEADS + h))*SEQ + s)*HDIM;
    dst[i]      = tf32_rna((x1*cv - x2*sv) * scale);
    dst[i + 64] = tf32_rna((x2*cv + x1*sv) * scale);
}

// ---------------------------------------------------------------------------
// RoPE K + copy V (tf32-rounded), -> [B,KV,S,D]
// ---------------------------------------------------------------------------
__global__ void rope_kv_kernel(const float* __restrict__ proj,
                               const int* __restrict__ seq_pos,
                               float* __restrict__ Ko, float* __restrict__ Vo)
{
    int idx = blockIdx.x*blockDim.x + threadIdx.x;
    if (idx >= BATCH*SEQ*NKV*64) return;
    int i  = idx & 63;
    int kv = (idx >> 6) & 3;
    int s  = (idx >> 8) & 2047;
    int b  = idx >> 19;

    float pos  = (float)seq_pos[b*SEQ + s];
    float frac = (float)(2*i) * (1.0f/128.0f);
    float ts   = powf(10000.0f, frac);
    float ang  = pos / ts;
    float sv, cv; sincosf(ang, &sv, &cv);

    const float* src = proj + (size_t)(b*SEQ + s)*KVDIM + kv*(2*HDIM);
    float k1 = src[i],       k2 = src[i + 64];
    float v1 = src[128 + i], v2 = src[192 + i];

    size_t base = (((size_t)(b*NKV + kv))*SEQ + s)*HDIM;
    Ko[base + i]      = tf32_rna(k1*cv - k2*sv);
    Ko[base + i + 64] = tf32_rna(k2*cv + k1*sv);
    Vo[base + i]      = tf32_rna(v1);
    Vo[base + i + 64] = tf32_rna(v2);
}

// ---------------------------------------------------------------------------
// Flash attention (tf32 mma.sync), causal, GQA. 256 thr = 8 warps.
// Writes output directly as fp16 [B,S,H*D].
// ---------------------------------------------------------------------------
#define FQ_STR 132
#define FP_STR 76

__global__ __launch_bounds__(256, 1) void flash_tf32(
    const float* __restrict__ Q, const float* __restrict__ Kg,
    const float* __restrict__ Vg, __half* __restrict__ X)
{
    extern __shared__ float sm[];
    float* Qs   = sm;
    float* Ks   = Qs + 64*FQ_STR;
    float* Vs   = Ks + 64*FQ_STR;
    float* Ps   = Vs + 64*FQ_STR;
    float* redm = Ps + 64*FP_STR;
    float* reds = redm + 128;

    const int qt  = 31 - blockIdx.x;
    const int h   = blockIdx.y;
    const int b   = blockIdx.z;
    const int kvh = h >> 2;
    const int q0  = qt * 64;

    const int tid  = threadIdx.x;
    const int lane = tid & 31, wid = tid >> 5;
    const int wr   = wid >> 1, wc = wid & 1;
    const int gr   = lane >> 2, qd = lane & 3;
    const int r0   = wr*16 + gr, r1 = r0 + 8;

    const float* qb = Q  + ((size_t)(b*NHEADS + h)*SEQ + q0)*HDIM;
    const float* kb = Kg + (size_t)(b*NKV + kvh)*SEQ*HDIM;
    const float* vb = Vg + (size_t)(b*NKV + kvh)*SEQ*HDIM;

    #pragma unroll
    for (int i = 0; i < 8; i++) {
        int slot = tid + i*256;
        int r = slot >> 5, c = (slot & 31)*4;
        *(float4*)(Qs + r*FQ_STR + c) = *(const float4*)(qb + r*HDIM + c);
    }

    float o[8][4];
    #pragma unroll
    for (int i = 0; i < 8; i++)
        #pragma unroll
        for (int j = 0; j < 4; j++) o[i][j] = 0.f;
    float m0 = -INFINITY, m1 = -INFINITY, l0 = 0.f, l1 = 0.f;

    for (int kt = 0; kt <= qt; kt++) {
        __syncthreads();
        const float* kp = kb + (size_t)kt*64*HDIM;
        const float* vp = vb + (size_t)kt*64*HDIM;
        #pragma unroll
        for (int i = 0; i < 8; i++) {
            int slot = tid + i*256;
            int r = slot >> 5, c = (slot & 31)*4;
            *(float4*)(Ks + r*FQ_STR + c) = *(const float4*)(kp + r*HDIM + c);
            *(float4*)(Vs + r*FQ_STR + c) = *(const float4*)(vp + r*HDIM + c);
        }
        __syncthreads();

        float s[4][4];
        #pragma unroll
        for (int nt = 0; nt < 4; nt++)
            #pragma unroll
            for (int j = 0; j < 4; j++) s[nt][j] = 0.f;

        #pragma unroll
        for (int ks = 0; ks < 16; ks++) {
            const int k = ks*8;
            uint32_t a[4];
            a[0] = fu(Qs[r0*FQ_STR + k     + qd]);
            a[1] = fu(Qs[r1*FQ_STR + k     + qd]);
            a[2] = fu(Qs[r0*FQ_STR + k + 4 + qd]);
            a[3] = fu(Qs[r1*FQ_STR + k + 4 + qd]);
            #pragma unroll
            for (int nt = 0; nt < 4; nt++) {
                int cn = wc*32 + nt*8 + gr;
                uint32_t bf[2];
                bf[0] = fu(Ks[cn*FQ_STR + k     + qd]);
                bf[1] = fu(Ks[cn*FQ_STR + k + 4 + qd]);
                mma_tf32(s[nt], a, bf);
            }
        }

        if (kt == qt) {
            #pragma unroll
            for (int nt = 0; nt < 4; nt++) {
                int cg = kt*64 + wc*32 + nt*8 + 2*qd;
                if (cg     > q0 + r0) s[nt][0] = -1e30f;
                if (cg + 1 > q0 + r0) s[nt][1] = -1e30f;
                if (cg     > q0 + r1) s[nt][2] = -1e30f;
                if (cg + 1 > q0 + r1) s[nt][3] = -1e30f;
            }
        }

        float mx0 = -INFINITY, mx1 = -INFINITY;
        #pragma unroll
        for (int nt = 0; nt < 4; nt++) {
            mx0 = fmaxf(mx0, fmaxf(s[nt][0], s[nt][1]));
            mx1 = fmaxf(mx1, fmaxf(s[nt][2], s[nt][3]));
        }
        mx0 = fmaxf(mx0, __shfl_xor_sync(0xffffffffu, mx0, 1));
        mx0 = fmaxf(mx0, __shfl_xor_sync(0xffffffffu, mx0, 2));
        mx1 = fmaxf(mx1, __shfl_xor_sync(0xffffffffu, mx1, 1));
        mx1 = fmaxf(mx1, __shfl_xor_sync(0xffffffffu, mx1, 2));
        if (qd == 0) { redm[wc*64 + r0] = mx0; redm[wc*64 + r1] = mx1; }
        __syncthreads();
        float nm0 = fmaxf(m0, fmaxf(mx0, redm[(wc ^ 1)*64 + r0]));
        float nm1 = fmaxf(m1, fmaxf(mx1, redm[(wc ^ 1)*64 + r1]));
        float corr0 = __expf(m0 - nm0), corr1 = __expf(m1 - nm1);

        float sum0 = 0.f, sum1 = 0.f;
        #pragma unroll
        for (int nt = 0; nt < 4; nt++) {
            float p0 = tf32_rna(__expf(s[nt][0] - nm0));
            float p1 = tf32_rna(__expf(s[nt][1] - nm0));
            float p2 = tf32_rna(__expf(s[nt][2] - nm1));
            float p3 = tf32_rna(__expf(s[nt][3] - nm1));
            sum0 += p0 + p1; sum1 += p2 + p3;
            int cc = wc*32 + nt*8 + 2*qd;
            *(float2*)(Ps + r0*FP_STR + cc) = make_float2(p0, p1);
            *(float2*)(Ps + r1*FP_STR + cc) = make_float2(p2, p3);
        }
        sum0 += __shfl_xor_sync(0xffffffffu, sum0, 1);
        sum0 += __shfl_xor_sync(0xffffffffu, sum0, 2);
        sum1 += __shfl_xor_sync(0xffffffffu, sum1, 1);
        sum1 += __shfl_xor_sync(0xffffffffu, sum1, 2);
        if (qd == 0) { reds[wc*64 + r0] = sum0; reds[wc*64 + r1] = sum1; }
        __syncthreads();
        l0 = l0*corr0 + sum0 + reds[(wc ^ 1)*64 + r0];
        l1 = l1*corr1 + sum1 + reds[(wc ^ 1)*64 + r1];
        m0 = nm0; m1 = nm1;

        #pragma unroll
        for (int nt = 0; nt < 8; nt++) {
            o[nt][0] *= corr0; o[nt][1] *= corr0;
            o[nt][2] *= corr1; o[nt][3] *= corr1;
        }

        #pragma unroll
        for (int ks = 0; ks < 8; ks++) {
            const int k = ks*8;
            uint32_t a[4];
            a[0] = fu(Ps[r0*FP_STR + k     + qd]);
            a[1] = fu(Ps[r1*FP_STR + k     + qd]);
            a[2] = fu(Ps[r0*FP_STR + k + 4 + qd]);
            a[3] = fu(Ps[r1*FP_STR + k + 4 + qd]);
            #pragma unroll
            for (int nt = 0; nt < 8; nt++) {
                int cn = wc*64 + nt*8 + gr;
                uint32_t bf[2];
                bf[0] = fu(Vs[(k     + qd)*FQ_STR + cn]);
                bf[1] = fu(Vs[(k + 4 + qd)*FQ_STR + cn]);
                mma_tf32(o[nt], a, bf);
            }
        }
    }

    float inv0 = 1.f / l0, inv1 = 1.f / l1;
    size_t rb0 = ((size_t)(b*SEQ + q0 + r0))*DMODEL + h*HDIM;
    size_t rb1 = ((size_t)(b*SEQ + q0 + r1))*DMODEL + h*HDIM;
    #pragma unroll
    for (int nt = 0; nt < 8; nt++) {
        int cc = wc*64 + nt*8 + 2*qd;
        *(__half2*)(X + rb0 + cc) = __floats2half2_rn(o[nt][0]*inv0, o[nt][1]*inv0);
        *(__half2*)(X + rb1 + cc) = __floats2half2_rn(o[nt][2]*inv1, o[nt][3]*inv1);
    }
}

// ---------------------------------------------------------------------------
// Launch
// ---------------------------------------------------------------------------
extern "C" void kernel_launch(void* const* d_in, const int* in_sizes, int n_in,
                              void* d_out, int out_size)
{
    const float* inputs  = (const float*)d_in[0];
    const int*   seq_pos = (const int*)  d_in[1];
    const float* wq      = (const float*)d_in[2];
    const float* bq      = (const float*)d_in[3];
    const float* wkv     = (const float*)d_in[4];
    const float* bkv     = (const float*)d_in[5];
    const float* wo      = (const float*)d_in[6];
    const float* bo      = (const float*)d_in[7];
    float* out = (float*)d_out;

    __half *in_h, *wq_h, *wkv_h, *wo_h, *x_h;
    float *projq, *projkv, *q, *k, *v;
    cudaGetSymbolAddress((void**)&in_h,  g_in_h);
    cudaGetSymbolAddress((void**)&wq_h,  g_wq_h);
    cudaGetSymbolAddress((void**)&wkv_h, g_wkv_h);
    cudaGetSymbolAddress((void**)&wo_h,  g_wo_h);
    cudaGetSymbolAddress((void**)&x_h,   g_x_h);
    cudaGetSymbolAddress((void**)&projq,  g_projq);
    cudaGetSymbolAddress((void**)&projkv, g_projkv);
    cudaGetSymbolAddress((void**)&q,      g_q);
    cudaGetSymbolAddress((void**)&k,      g_k);
    cudaGetSymbolAddress((void**)&v,      g_v);

    const int GEMM_SMEM  = 2*HBUF*2;                              // 73728 B
    const int FLASH_SMEM = (3*64*FQ_STR + 64*FP_STR + 256)*4;     // 121856 B
    cudaFuncSetAttribute(gemm_f16,
                         cudaFuncAttributeMaxDynamicSharedMemorySize, GEMM_SMEM);
    cudaFuncSetAttribute(flash_tf32,
                         cudaFuncAttributeMaxDynamicSharedMemorySize, FLASH_SMEM);

    // 0) staging: activations -> fp16; weights -> transposed fp16
    cvt_f16<<<(M_TOK*DMODEL/4)/256, 256>>>((const float4*)inputs,
        (__half2*)in_h, M_TOK*DMODEL/4);
    tcvt_f16<<<dim3(DMODEL/32, DMODEL/32), dim3(32,8)>>>(wq,  wq_h,  DMODEL, DMODEL);
    tcvt_f16<<<dim3(KVDIM/32,  DMODEL/32), dim3(32,8)>>>(wkv, wkv_h, DMODEL, KVDIM);
    tcvt_f16<<<dim3(DMODEL/32, DMODEL/32), dim3(32,8)>>>(wo,  wo_h,  DMODEL, DMODEL);

    // 1) projections (fp16 HMMA, fp32 accum)
    gemm_f16<<<dim3(DMODEL/128, M_TOK/128), 256, GEMM_SMEM>>>(
        in_h, wq_h, bq, projq, M_TOK, DMODEL, DMODEL);
    gemm_f16<<<dim3(KVDIM/128, M_TOK/128), 256, GEMM_SMEM>>>(
        in_h, wkv_h, bkv, projkv, M_TOK, KVDIM, DMODEL);

    // 2) RoPE + relayout
    rope_q_kernel<<<(BATCH*SEQ*NHEADS*64)/256, 256>>>(projq, seq_pos, q);
    rope_kv_kernel<<<(BATCH*SEQ*NKV*64)/256, 256>>>(projkv, seq_pos, k, v);

    // 3) flash attention (tf32 mma.sync), fp16 output
    flash_tf32<<<dim3(SEQ/64, NHEADS, BATCH), 256, FLASH_SMEM>>>(q, k, v, x_h);

    // 4) output projection (fp16 HMMA)
    gemm_f16<<<dim3(DMODEL/128, M_TOK/128), 256, GEMM_SMEM>>>(
        x_h, wo_h, bo, out, M_TOK, DMODEL, DMODEL);
}

// round 5
// speedup vs baseline: 5.1170x; 1.3918x over previous
#include <cuda_runtime.h>
#include <cuda_fp16.h>
#include <math.h>
#include <stdint.h>

// ---------------------------------------------------------------------------
// Problem constants
// ---------------------------------------------------------------------------
#define BATCH    2
#define SEQ      2048
#define DMODEL   2048
#define NHEADS   16
#define NKV      4
#define HDIM     128
#define M_TOK    (BATCH*SEQ)           // 4096
#define KVDIM    (NKV*2*HDIM)          // 1024

// ---------------------------------------------------------------------------
// Scratch
// ---------------------------------------------------------------------------
__device__ __half g_in_h [M_TOK*DMODEL];
__device__ __half g_wq_h [DMODEL*DMODEL];    // transposed [N,K]
__device__ __half g_wkv_h[KVDIM*DMODEL];     // transposed [N,K]
__device__ __half g_wo_h [DMODEL*DMODEL];    // transposed [N,K]
__device__ __half g_x_h  [M_TOK*DMODEL];     // attention out, fp16
__device__ __half g_q [BATCH*NHEADS*SEQ*HDIM];  // fp16 [B,H,S,D]
__device__ __half g_k [BATCH*NKV*SEQ*HDIM];     // fp16 [B,KV,S,D]
__device__ __half g_vt[BATCH*NKV*HDIM*SEQ];     // fp16 [B,KV,D,S] (transposed)
__device__ float g_projq [M_TOK*DMODEL];
__device__ float g_projkv[M_TOK*KVDIM];

// ---------------------------------------------------------------------------
// Helpers
// ---------------------------------------------------------------------------
__device__ __forceinline__ void mma_f16(float c[4], const uint32_t a[4], const uint32_t b[2]) {
    asm volatile(
        "mma.sync.aligned.m16n8k16.row.col.f32.f16.f16.f32 "
        "{%0,%1,%2,%3},{%4,%5,%6,%7},{%8,%9},{%0,%1,%2,%3};"
        : "+f"(c[0]), "+f"(c[1]), "+f"(c[2]), "+f"(c[3])
        : "r"(a[0]), "r"(a[1]), "r"(a[2]), "r"(a[3]), "r"(b[0]), "r"(b[1]));
}

__device__ __forceinline__ void cpa16(void* smem, const void* g) {
    uint32_t s = (uint32_t)__cvta_generic_to_shared(smem);
    asm volatile("cp.async.cg.shared.global [%0], [%1], 16;\n" :: "r"(s), "l"(g));
}
__device__ __forceinline__ void cp_commit() { asm volatile("cp.async.commit_group;"); }
__device__ __forceinline__ void cp_wait1()  { asm volatile("cp.async.wait_group 1;"); }
__device__ __forceinline__ void cp_wait0()  { asm volatile("cp.async.wait_group 0;"); }

// ---------------------------------------------------------------------------
// Staging: fp32 -> fp16 (same layout)
// ---------------------------------------------------------------------------
__global__ void cvt_f16(const float4* __restrict__ src, __half2* __restrict__ dst, int n4)
{
    int i = blockIdx.x*blockDim.x + threadIdx.x;
    if (i >= n4) return;
    float4 x = src[i];
    dst[2*i]   = __floats2half2_rn(x.x, x.y);
    dst[2*i+1] = __floats2half2_rn(x.z, x.w);
}

// ---------------------------------------------------------------------------
// Staging: W[K,N] fp32 -> transposed fp16 [N,K]
// ---------------------------------------------------------------------------
__global__ void tcvt_f16(const float* __restrict__ W, __half* __restrict__ T, int K, int N)
{
    __shared__ float t[32][33];
    int n0 = blockIdx.x*32, k0 = blockIdx.y*32;
    int tx = threadIdx.x, ty = threadIdx.y;  // 32 x 8
    #pragma unroll
    for (int i = 0; i < 4; i++)
        t[ty + 8*i][tx] = W[(size_t)(k0 + ty + 8*i)*N + n0 + tx];
    __syncthreads();
    #pragma unroll
    for (int i = 0; i < 4; i++)
        T[(size_t)(n0 + ty + 8*i)*K + k0 + tx] = __float2half_rn(t[tx][ty + 8*i]);
}

// ---------------------------------------------------------------------------
// fp16 GEMM (fp32 accum): C[M,N] = A[M,K] @ B[N,K]^T + bias
// ---------------------------------------------------------------------------
#define HSTR 72
#define HBUF 18432

__global__ __launch_bounds__(256) void gemm_f16(
    const __half* __restrict__ A, const __half* __restrict__ B,
    const float* __restrict__ bias, float* __restrict__ C,
    int M, int N, int K)
{
    extern __shared__ __half sh[];
    const int tid  = threadIdx.x;
    const int lane = tid & 31, wid = tid >> 5;
    const int wr   = wid >> 2, wc = wid & 3;
    const int gr   = lane >> 2, qd = lane & 3;
    const int bm   = blockIdx.y*128, bn = blockIdx.x*128;

    float acc[4][4][4];
    #pragma unroll
    for (int i = 0; i < 4; i++)
        #pragma unroll
        for (int j = 0; j < 4; j++)
            #pragma unroll
            for (int r = 0; r < 4; r++) acc[i][j][r] = 0.f;

    auto load_tile = [&](int buf, int k0) {
        __half* sA = sh + buf*HBUF;
        __half* sB = sA + 128*HSTR;
        #pragma unroll
        for (int i = 0; i < 4; i++) {
            int slot = tid + i*256;
            int r = slot >> 3, c8 = (slot & 7)*8;
            cpa16(sA + r*HSTR + c8, A + (size_t)(bm + r)*K + k0 + c8);
            cpa16(sB + r*HSTR + c8, B + (size_t)(bn + r)*K + k0 + c8);
        }
        cp_commit();
    };

    load_tile(0, 0);

    const int KT = K / 64;
    int buf = 0;
    for (int it = 0; it < KT; it++) {
        if (it + 1 < KT) { load_tile(buf ^ 1, (it + 1)*64); cp_wait1(); }
        else             { cp_wait0(); }
        __syncthreads();

        const __half* sA = sh + buf*HBUF;
        const __half* sB = sA + 128*HSTR;

        #pragma unroll
        for (int ks = 0; ks < 4; ks++) {
            const int k = ks*16;
            uint32_t a[4][4], b[4][2];
            #pragma unroll
            for (int mt = 0; mt < 4; mt++) {
                int r = wr*64 + mt*16 + gr;
                a[mt][0] = *(const uint32_t*)(sA + (r  )*HSTR + k     + 2*qd);
                a[mt][1] = *(const uint32_t*)(sA + (r+8)*HSTR + k     + 2*qd);
                a[mt][2] = *(const uint32_t*)(sA + (r  )*HSTR + k + 8 + 2*qd);
                a[mt][3] = *(const uint32_t*)(sA + (r+8)*HSTR + k + 8 + 2*qd);
            }
            #pragma unroll
            for (int nt = 0; nt < 4; nt++) {
                int n = wc*32 + nt*8 + gr;
                b[nt][0] = *(const uint32_t*)(sB + n*HSTR + k     + 2*qd);
                b[nt][1] = *(const uint32_t*)(sB + n*HSTR + k + 8 + 2*qd);
            }
            #pragma unroll
            for (int mt = 0; mt < 4; mt++)
                #pragma unroll
                for (int nt = 0; nt < 4; nt++)
                    mma_f16(acc[mt][nt], a[mt], b[nt]);
        }
        __syncthreads();
        buf ^= 1;
    }

    #pragma unroll
    for (int nt = 0; nt < 4; nt++) {
        int col = bn + wc*32 + nt*8 + 2*qd;
        float2 bv = *(const float2*)(bias + col);
        #pragma unroll
        for (int mt = 0; mt < 4; mt++) {
            int row = bm + wr*64 + mt*16 + gr;
            *(float2*)(C + (size_t)row*N + col) =
                make_float2(acc[mt][nt][0] + bv.x, acc[mt][nt][1] + bv.y);
            *(float2*)(C + (size_t)(row + 8)*N + col) =
                make_float2(acc[mt][nt][2] + bv.x, acc[mt][nt][3] + bv.y);
        }
    }
}

// ---------------------------------------------------------------------------
// RoPE Q (folds 1/sqrt(HD)), fp16 out -> [B,H,S,D]
// ---------------------------------------------------------------------------
__global__ void rope_q_kernel(const float* __restrict__ proj,
                              const int* __restrict__ seq_pos,
                              __half* __restrict__ Qo)
{
    int idx = blockIdx.x*blockDim.x + threadIdx.x;
    if (idx >= BATCH*SEQ*NHEADS*64) return;
    int i = idx & 63;
    int h = (idx >> 6) & 15;
    int s = (idx >> 10) & 2047;
    int b = idx >> 21;

    float pos  = (float)seq_pos[b*SEQ + s];
    float frac = (float)(2*i) * (1.0f/128.0f);
    float ts   = powf(10000.0f, frac);
    float ang  = pos / ts;
    float sv, cv; sincosf(ang, &sv, &cv);

    const float* src = proj + (size_t)(b*SEQ + s)*DMODEL + h*HDIM;
    float x1 = src[i], x2 = src[i + 64];
    const float scale = 0.08838834764831845f;
    __half* dst = Qo + (((size_t)(b*NHEADS + h))*SEQ + s)*HDIM;
    dst[i]      = __float2half_rn((x1*cv - x2*sv) * scale);
    dst[i + 64] = __float2half_rn((x2*cv + x1*sv) * scale);
}

// ---------------------------------------------------------------------------
// RoPE K, fp16 out -> [B,KV,S,D]
// ---------------------------------------------------------------------------
__global__ void rope_k_kernel(const float* __restrict__ proj,
                              const int* __restrict__ seq_pos,
                              __half* __restrict__ Ko)
{
    int idx = blockIdx.x*blockDim.x + threadIdx.x;
    if (idx >= BATCH*SEQ*NKV*64) return;
    int i  = idx & 63;
    int kv = (idx >> 6) & 3;
    int s  = (idx >> 8) & 2047;
    int b  = idx >> 19;

    float pos  = (float)seq_pos[b*SEQ + s];
    float frac = (float)(2*i) * (1.0f/128.0f);
    float ts   = powf(10000.0f, frac);
    float ang  = pos / ts;
    float sv, cv; sincosf(ang, &sv, &cv);

    const float* src = proj + (size_t)(b*SEQ + s)*KVDIM + kv*(2*HDIM);
    float k1 = src[i], k2 = src[i + 64];

    __half* dst = Ko + (((size_t)(b*NKV + kv))*SEQ + s)*HDIM;
    dst[i]      = __float2half_rn(k1*cv - k2*sv);
    dst[i + 64] = __float2half_rn(k2*cv + k1*sv);
}

// ---------------------------------------------------------------------------
// V: extract from projkv, transpose -> fp16 [B,KV,D,S]
// grid (SEQ/32, HDIM/32, BATCH*NKV), block 32x8
// ---------------------------------------------------------------------------
__global__ void vt_kernel(const float* __restrict__ proj, __half* __restrict__ Vt)
{
    __shared__ float t[32][33];
    int s0 = blockIdx.x*32, d0 = blockIdx.y*32;
    int bkv = blockIdx.z;
    int b = bkv >> 2, kv = bkv & 3;
    int tx = threadIdx.x, ty = threadIdx.y;

    const float* src = proj + (size_t)(b*SEQ)*KVDIM + kv*(2*HDIM) + 128;
    #pragma unroll
    for (int i = 0; i < 4; i++)
        t[ty + 8*i][tx] = src[(size_t)(s0 + ty + 8*i)*KVDIM + d0 + tx];
    __syncthreads();
    __half* dst = Vt + ((size_t)bkv*HDIM)*SEQ;
    #pragma unroll
    for (int i = 0; i < 4; i++)
        dst[(size_t)(d0 + ty + 8*i)*SEQ + s0 + tx] = __float2half_rn(t[tx][ty + 8*i]);
}

// ---------------------------------------------------------------------------
// Flash attention, fp16 HMMA, causal, GQA. 256 thr = 8 warps.
// Q/K tiles [64 x 128] fp16 (QS stride), Vt tiles [128 x 64] fp16 (VS stride).
// K/Vt cp.async double-buffered. P fp16. Output fp16 [B,S,H*D].
// ---------------------------------------------------------------------------
#define QS 136
#define VS 72
#define PS 72
#define SMH_Q   0
#define SMH_K0  (64*QS)                 // 8704
#define SMH_K1  (SMH_K0 + 64*QS)
#define SMH_V0  (SMH_K1 + 64*QS)
#define SMH_V1  (SMH_V0 + 128*VS)
#define SMH_P   (SMH_V1 + 128*VS)
#define SMH_TOT (SMH_P + 64*PS)         // 49152 halves
#define FLASH_SMEM (SMH_TOT*2 + 1024)   // + 256 floats reductions

__global__ __launch_bounds__(256, 2) void flash_f16(
    const __half* __restrict__ Q, const __half* __restrict__ Kg,
    const __half* __restrict__ Vtg, __half* __restrict__ X)
{
    extern __shared__ __half smh[];
    float* redm = (float*)(smh + SMH_TOT);
    float* reds = redm + 128;

    const int qt  = 31 - blockIdx.x;
    const int h   = blockIdx.y;
    const int b   = blockIdx.z;
    const int kvh = h >> 2;
    const int q0  = qt * 64;

    const int tid  = threadIdx.x;
    const int lane = tid & 31, wid = tid >> 5;
    const int wr   = wid >> 1, wc = wid & 1;
    const int gr   = lane >> 2, qd = lane & 3;
    const int r0   = wr*16 + gr, r1 = r0 + 8;

    const __half* qb  = Q   + ((size_t)(b*NHEADS + h)*SEQ + q0)*HDIM;
    const __half* kb  = Kg  + (size_t)(b*NKV + kvh)*SEQ*HDIM;
    const __half* vtb = Vtg + (size_t)(b*NKV + kvh)*HDIM*SEQ;

    auto load_kv = [&](int buf, int kt) {
        __half* Ks = smh + (buf ? SMH_K1 : SMH_K0);
        __half* Vs = smh + (buf ? SMH_V1 : SMH_V0);
        const __half* kp = kb + (size_t)kt*64*HDIM;
        #pragma unroll
        for (int i = 0; i < 4; i++) {
            int slot = tid + i*256;
            int r = slot >> 4, c8 = (slot & 15)*8;
            cpa16(Ks + r*QS + c8, kp + r*HDIM + c8);
        }
        #pragma unroll
        for (int i = 0; i < 4; i++) {
            int slot = tid + i*256;
            int d = slot >> 3, c8 = (slot & 7)*8;
            cpa16(Vs + d*VS + c8, vtb + (size_t)d*SEQ + kt*64 + c8);
        }
        cp_commit();
    };

    // preamble: Q + first K/V tile as one group
    #pragma unroll
    for (int i = 0; i < 4; i++) {
        int slot = tid + i*256;
        int r = slot >> 4, c8 = (slot & 15)*8;
        cpa16(smh + SMH_Q + r*QS + c8, qb + r*HDIM + c8);
    }
    load_kv(0, 0);

    float o[8][4];
    #pragma unroll
    for (int i = 0; i < 8; i++)
        #pragma unroll
        for (int j = 0; j < 4; j++) o[i][j] = 0.f;
    float m0 = -INFINITY, m1 = -INFINITY, l0 = 0.f, l1 = 0.f;

    const __half* Qs = smh + SMH_Q;
    __half* Ps = smh + SMH_P;

    for (int kt = 0; kt <= qt; kt++) {
        const int buf = kt & 1;
        __syncthreads();          // prev PV done before prefetch overwrites
        if (kt < qt) { load_kv(buf ^ 1, kt + 1); cp_wait1(); }
        else         { cp_wait0(); }
        __syncthreads();

        const __half* Ks = smh + (buf ? SMH_K1 : SMH_K0);
        const __half* Vs = smh + (buf ? SMH_V1 : SMH_V0);

        // ---- S = Q K^T (fp16 k16) ----
        float s[4][4];
        #pragma unroll
        for (int nt = 0; nt < 4; nt++)
            #pragma unroll
            for (int j = 0; j < 4; j++) s[nt][j] = 0.f;

        #pragma unroll
        for (int ks = 0; ks < 8; ks++) {
            const int k = ks*16;
            uint32_t a[4];
            a[0] = *(const uint32_t*)(Qs + r0*QS + k     + 2*qd);
            a[1] = *(const uint32_t*)(Qs + r1*QS + k     + 2*qd);
            a[2] = *(const uint32_t*)(Qs + r0*QS + k + 8 + 2*qd);
            a[3] = *(const uint32_t*)(Qs + r1*QS + k + 8 + 2*qd);
            #pragma unroll
            for (int nt = 0; nt < 4; nt++) {
                int cn = wc*32 + nt*8 + gr;
                uint32_t bf[2];
                bf[0] = *(const uint32_t*)(Ks + cn*QS + k     + 2*qd);
                bf[1] = *(const uint32_t*)(Ks + cn*QS + k + 8 + 2*qd);
                mma_f16(s[nt], a, bf);
            }
        }

        if (kt == qt) {
            #pragma unroll
            for (int nt = 0; nt < 4; nt++) {
                int cg = kt*64 + wc*32 + nt*8 + 2*qd;
                if (cg     > q0 + r0) s[nt][0] = -1e30f;
                if (cg + 1 > q0 + r0) s[nt][1] = -1e30f;
                if (cg     > q0 + r1) s[nt][2] = -1e30f;
                if (cg + 1 > q0 + r1) s[nt][3] = -1e30f;
            }
        }

        // ---- online softmax ----
        float mx0 = -INFINITY, mx1 = -INFINITY;
        #pragma unroll
        for (int nt = 0; nt < 4; nt++) {
            mx0 = fmaxf(mx0, fmaxf(s[nt][0], s[nt][1]));
            mx1 = fmaxf(mx1, fmaxf(s[nt][2], s[nt][3]));
        }
        mx0 = fmaxf(mx0, __shfl_xor_sync(0xffffffffu, mx0, 1));
        mx0 = fmaxf(mx0, __shfl_xor_sync(0xffffffffu, mx0, 2));
        mx1 = fmaxf(mx1, __shfl_xor_sync(0xffffffffu, mx1, 1));
        mx1 = fmaxf(mx1, __shfl_xor_sync(0xffffffffu, mx1, 2));
        if (qd == 0) { redm[wc*64 + r0] = mx0; redm[wc*64 + r1] = mx1; }
        __syncthreads();
        float nm0 = fmaxf(m0, fmaxf(mx0, redm[(wc ^ 1)*64 + r0]));
        float nm1 = fmaxf(m1, fmaxf(mx1, redm[(wc ^ 1)*64 + r1]));
        float corr0 = __expf(m0 - nm0), corr1 = __expf(m1 - nm1);

        float sum0 = 0.f, sum1 = 0.f;
        #pragma unroll
        for (int nt = 0; nt < 4; nt++) {
            float p0 = __expf(s[nt][0] - nm0);
            float p1 = __expf(s[nt][1] - nm0);
            float p2 = __expf(s[nt][2] - nm1);
            float p3 = __expf(s[nt][3] - nm1);
            sum0 += p0 + p1; sum1 += p2 + p3;
            int cc = wc*32 + nt*8 + 2*qd;
            *(__half2*)(Ps + r0*PS + cc) = __floats2half2_rn(p0, p1);
            *(__half2*)(Ps + r1*PS + cc) = __floats2half2_rn(p2, p3);
        }
        sum0 += __shfl_xor_sync(0xffffffffu, sum0, 1);
        sum0 += __shfl_xor_sync(0xffffffffu, sum0, 2);
        sum1 += __shfl_xor_sync(0xffffffffu, sum1, 1);
        sum1 += __shfl_xor_sync(0xffffffffu, sum1, 2);
        if (qd == 0) { reds[wc*64 + r0] = sum0; reds[wc*64 + r1] = sum1; }
        __syncthreads();
        l0 = l0*corr0 + sum0 + reds[(wc ^ 1)*64 + r0];
        l1 = l1*corr1 + sum1 + reds[(wc ^ 1)*64 + r1];
        m0 = nm0; m1 = nm1;

        #pragma unroll
        for (int nt = 0; nt < 8; nt++) {
            o[nt][0] *= corr0; o[nt][1] *= corr0;
            o[nt][2] *= corr1; o[nt][3] *= corr1;
        }

        // ---- O += P V (fp16 k16, B = Vt[d][token]) ----
        #pragma unroll
        for (int ks = 0; ks < 4; ks++) {
            const int k = ks*16;
            uint32_t a[4];
            a[0] = *(const uint32_t*)(Ps + r0*PS + k     + 2*qd);
            a[1] = *(const uint32_t*)(Ps + r1*PS + k     + 2*qd);
            a[2] = *(const uint32_t*)(Ps + r0*PS + k + 8 + 2*qd);
            a[3] = *(const uint32_t*)(Ps + r1*PS + k + 8 + 2*qd);
            #pragma unroll
            for (int nt = 0; nt < 8; nt++) {
                int cn = wc*64 + nt*8 + gr;     // d index
                uint32_t bf[2];
                bf[0] = *(const uint32_t*)(Vs + cn*VS + k     + 2*qd);
                bf[1] = *(const uint32_t*)(Vs + cn*VS + k + 8 + 2*qd);
                mma_f16(o[nt], a, bf);
            }
        }
    }

    // ---- finalize, store fp16 [B,S,H*D] ----
    float inv0 = 1.f / l0, inv1 = 1.f / l1;
    size_t rb0 = ((size_t)(b*SEQ + q0 + r0))*DMODEL + h*HDIM;
    size_t rb1 = ((size_t)(b*SEQ + q0 + r1))*DMODEL + h*HDIM;
    #pragma unroll
    for (int nt = 0; nt < 8; nt++) {
        int cc = wc*64 + nt*8 + 2*qd;
        *(__half2*)(X + rb0 + cc) = __floats2half2_rn(o[nt][0]*inv0, o[nt][1]*inv0);
        *(__half2*)(X + rb1 + cc) = __floats2half2_rn(o[nt][2]*inv1, o[nt][3]*inv1);
    }
}

// ---------------------------------------------------------------------------
// Launch
// ---------------------------------------------------------------------------
extern "C" void kernel_launch(void* const* d_in, const int* in_sizes, int n_in,
                              void* d_out, int out_size)
{
    const float* inputs  = (const float*)d_in[0];
    const int*   seq_pos = (const int*)  d_in[1];
    const float* wq      = (const float*)d_in[2];
    const float* bq      = (const float*)d_in[3];
    const float* wkv     = (const float*)d_in[4];
    const float* bkv     = (const float*)d_in[5];
    const float* wo      = (const float*)d_in[6];
    const float* bo      = (const float*)d_in[7];
    float* out = (float*)d_out;

    __half *in_h, *wq_h, *wkv_h, *wo_h, *x_h, *q, *k, *vt;
    float *projq, *projkv;
    cudaGetSymbolAddress((void**)&in_h,  g_in_h);
    cudaGetSymbolAddress((void**)&wq_h,  g_wq_h);
    cudaGetSymbolAddress((void**)&wkv_h, g_wkv_h);
    cudaGetSymbolAddress((void**)&wo_h,  g_wo_h);
    cudaGetSymbolAddress((void**)&x_h,   g_x_h);
    cudaGetSymbolAddress((void**)&q,     g_q);
    cudaGetSymbolAddress((void**)&k,     g_k);
    cudaGetSymbolAddress((void**)&vt,    g_vt);
    cudaGetSymbolAddress((void**)&projq,  g_projq);
    cudaGetSymbolAddress((void**)&projkv, g_projkv);

    const int GEMM_SMEM = 2*HBUF*2;     // 73728 B
    cudaFuncSetAttribute(gemm_f16,
                         cudaFuncAttributeMaxDynamicSharedMemorySize, GEMM_SMEM);
    cudaFuncSetAttribute(flash_f16,
                         cudaFuncAttributeMaxDynamicSharedMemorySize, FLASH_SMEM);

    // 0) staging
    cvt_f16<<<(M_TOK*DMODEL/4)/256, 256>>>((const float4*)inputs,
        (__half2*)in_h, M_TOK*DMODEL/4);
    tcvt_f16<<<dim3(DMODEL/32, DMODEL/32), dim3(32,8)>>>(wq,  wq_h,  DMODEL, DMODEL);
    tcvt_f16<<<dim3(KVDIM/32,  DMODEL/32), dim3(32,8)>>>(wkv, wkv_h, DMODEL, KVDIM);
    tcvt_f16<<<dim3(DMODEL/32, DMODEL/32), dim3(32,8)>>>(wo,  wo_h,  DMODEL, DMODEL);

    // 1) projections
    gemm_f16<<<dim3(DMODEL/128, M_TOK/128), 256, GEMM_SMEM>>>(
        in_h, wq_h, bq, projq, M_TOK, DMODEL, DMODEL);
    gemm_f16<<<dim3(KVDIM/128, M_TOK/128), 256, GEMM_SMEM>>>(
        in_h, wkv_h, bkv, projkv, M_TOK, KVDIM, DMODEL);

    // 2) RoPE + relayout (fp16), V transpose
    rope_q_kernel<<<(BATCH*SEQ*NHEADS*64)/256, 256>>>(projq, seq_pos, q);
    rope_k_kernel<<<(BATCH*SEQ*NKV*64)/256, 256>>>(projkv, seq_pos, k);
    vt_kernel<<<dim3(SEQ/32, HDIM/32, BATCH*NKV), dim3(32,8)>>>(projkv, vt);

    // 3) flash attention (fp16 HMMA)
    flash_f16<<<dim3(SEQ/64, NHEADS, BATCH), 256, FLASH_SMEM>>>(q, k, vt, x_h);

    // 4) output projection
    gemm_f16<<<dim3(DMODEL/128, M_TOK/128), 256, GEMM_SMEM>>>(
        x_h, wo_h, bo, out, M_TOK, DMODEL, DMODEL);
}

// round 6
// speedup vs baseline: 5.6733x; 1.1087x over previous
#include <cuda_runtime.h>
#include <cuda_fp16.h>
#include <math.h>
#include <stdint.h>

// ---------------------------------------------------------------------------
// Problem constants
// ---------------------------------------------------------------------------
#define BATCH    2
#define SEQ      2048
#define DMODEL   2048
#define NHEADS   16
#define NKV      4
#define HDIM     128
#define M_TOK    (BATCH*SEQ)           // 4096
#define KVDIM    (NKV*2*HDIM)          // 1024
#define NQKV     (DMODEL + KVDIM)      // 3072

// ---------------------------------------------------------------------------
// Scratch
// ---------------------------------------------------------------------------
__device__ __half g_in_h  [M_TOK*DMODEL];
__device__ __half g_wqkv_h[NQKV*DMODEL];     // transposed [N,K]: rows 0-2047 = wq, 2048+ = wkv
__device__ __half g_wo_h  [DMODEL*DMODEL];   // transposed [N,K]
__device__ __half g_x_h   [M_TOK*DMODEL];    // attention out, fp16
__device__ __half g_q [BATCH*NHEADS*SEQ*HDIM];  // fp16 [B,H,S,D]
__device__ __half g_k [BATCH*NKV*SEQ*HDIM];     // fp16 [B,KV,S,D]
__device__ __half g_vt[BATCH*NKV*HDIM*SEQ];     // fp16 [B,KV,D,S]

// ---------------------------------------------------------------------------
// Helpers
// ---------------------------------------------------------------------------
__device__ __forceinline__ void mma_f16(float c[4], const uint32_t a[4], const uint32_t b[2]) {
    asm volatile(
        "mma.sync.aligned.m16n8k16.row.col.f32.f16.f16.f32 "
        "{%0,%1,%2,%3},{%4,%5,%6,%7},{%8,%9},{%0,%1,%2,%3};"
        : "+f"(c[0]), "+f"(c[1]), "+f"(c[2]), "+f"(c[3])
        : "r"(a[0]), "r"(a[1]), "r"(a[2]), "r"(a[3]), "r"(b[0]), "r"(b[1]));
}

__device__ __forceinline__ void cpa16(void* smem, const void* g) {
    uint32_t s = (uint32_t)__cvta_generic_to_shared(smem);
    asm volatile("cp.async.cg.shared.global [%0], [%1], 16;\n" :: "r"(s), "l"(g));
}
__device__ __forceinline__ void cp_commit() { asm volatile("cp.async.commit_group;"); }
__device__ __forceinline__ void cp_wait1()  { asm volatile("cp.async.wait_group 1;"); }
__device__ __forceinline__ void cp_wait0()  { asm volatile("cp.async.wait_group 0;"); }

// ---------------------------------------------------------------------------
// Staging: fp32 -> fp16 (same layout)
// ---------------------------------------------------------------------------
__global__ void cvt_f16(const float4* __restrict__ src, __half2* __restrict__ dst, int n4)
{
    int i = blockIdx.x*blockDim.x + threadIdx.x;
    if (i >= n4) return;
    float4 x = src[i];
    dst[2*i]   = __floats2half2_rn(x.x, x.y);
    dst[2*i+1] = __floats2half2_rn(x.z, x.w);
}

// ---------------------------------------------------------------------------
// Staging: W[K,N] fp32 -> transposed fp16 [N,K]
// ---------------------------------------------------------------------------
__global__ void tcvt_f16(const float* __restrict__ W, __half* __restrict__ T, int K, int N)
{
    __shared__ float t[32][33];
    int n0 = blockIdx.x*32, k0 = blockIdx.y*32;
    int tx = threadIdx.x, ty = threadIdx.y;  // 32 x 8
    #pragma unroll
    for (int i = 0; i < 4; i++)
        t[ty + 8*i][tx] = W[(size_t)(k0 + ty + 8*i)*N + n0 + tx];
    __syncthreads();
    #pragma unroll
    for (int i = 0; i < 4; i++)
        T[(size_t)(n0 + ty + 8*i)*K + k0 + tx] = __float2half_rn(t[tx][ty + 8*i]);
}

// ---------------------------------------------------------------------------
// Shared GEMM mainloop macro bits
// ---------------------------------------------------------------------------
#define HSTR 72
#define HBUF 18432
#define TSTR 132   // fp32 epilogue tile stride

// ---------------------------------------------------------------------------
// Fused QKV projection: C = A @ Wqkv^T + bias, then rope Q/K + transpose V,
// writing fp16 q [B,H,S,D], k [B,KV,S,D], vt [B,KV,D,S] directly.
// grid (24, 32); region by bn: [0,2048) Q heads, [2048,3072) KV blocks.
// ---------------------------------------------------------------------------
__global__ __launch_bounds__(256, 2) void gemm_qkv(
    const __half* __restrict__ A, const __half* __restrict__ B,
    const float* __restrict__ bq, const float* __restrict__ bkv,
    const int* __restrict__ seq_pos,
    __half* __restrict__ Qo, __half* __restrict__ Ko, __half* __restrict__ Vt)
{
    extern __shared__ __half sh[];
    const int tid  = threadIdx.x;
    const int lane = tid & 31, wid = tid >> 5;
    const int wr   = wid >> 2, wc = wid & 3;
    const int gr   = lane >> 2, qd = lane & 3;
    const int bm   = blockIdx.y*128, bn = blockIdx.x*128;
    const int K    = DMODEL;

    float acc[4][4][4];
    #pragma unroll
    for (int i = 0; i < 4; i++)
        #pragma unroll
        for (int j = 0; j < 4; j++)
            #pragma unroll
            for (int r = 0; r < 4; r++) acc[i][j][r] = 0.f;

    auto load_tile = [&](int buf, int k0) {
        __half* sA = sh + buf*HBUF;
        __half* sB = sA + 128*HSTR;
        #pragma unroll
        for (int i = 0; i < 4; i++) {
            int slot = tid + i*256;
            int r = slot >> 3, c8 = (slot & 7)*8;
            cpa16(sA + r*HSTR + c8, A + (size_t)(bm + r)*K + k0 + c8);
            cpa16(sB + r*HSTR + c8, B + (size_t)(bn + r)*K + k0 + c8);
        }
        cp_commit();
    };

    load_tile(0, 0);

    const int KT = K / 64;
    int buf = 0;
    for (int it = 0; it < KT; it++) {
        if (it + 1 < KT) { load_tile(buf ^ 1, (it + 1)*64); cp_wait1(); }
        else             { cp_wait0(); }
        __syncthreads();

        const __half* sA = sh + buf*HBUF;
        const __half* sB = sA + 128*HSTR;

        #pragma unroll
        for (int ks = 0; ks < 4; ks++) {
            const int k = ks*16;
            uint32_t a[4][4], b[4][2];
            #pragma unroll
            for (int mt = 0; mt < 4; mt++) {
                int r = wr*64 + mt*16 + gr;
                a[mt][0] = *(const uint32_t*)(sA + (r  )*HSTR + k     + 2*qd);
                a[mt][1] = *(const uint32_t*)(sA + (r+8)*HSTR + k     + 2*qd);
                a[mt][2] = *(const uint32_t*)(sA + (r  )*HSTR + k + 8 + 2*qd);
                a[mt][3] = *(const uint32_t*)(sA + (r+8)*HSTR + k + 8 + 2*qd);
            }
            #pragma unroll
            for (int nt = 0; nt < 4; nt++) {
                int n = wc*32 + nt*8 + gr;
                b[nt][0] = *(const uint32_t*)(sB + n*HSTR + k     + 2*qd);
                b[nt][1] = *(const uint32_t*)(sB + n*HSTR + k + 8 + 2*qd);
            }
            #pragma unroll
            for (int mt = 0; mt < 4; mt++)
                #pragma unroll
                for (int nt = 0; nt < 4; nt++)
                    mma_f16(acc[mt][nt], a[mt], b[nt]);
        }
        __syncthreads();
        buf ^= 1;
    }

    // ---- epilogue: acc + bias -> smem fp32 tile ----
    float* tile = (float*)sh;   // 128 x TSTR floats = 67584 B (fits in 73728)
    const float* bias = (bn < DMODEL) ? (bq + bn) : (bkv + bn - DMODEL);
    #pragma unroll
    for (int nt = 0; nt < 4; nt++) {
        int col = wc*32 + nt*8 + 2*qd;
        float2 bv = *(const float2*)(bias + col);
        #pragma unroll
        for (int mt = 0; mt < 4; mt++) {
            int r = wr*64 + mt*16 + gr;
            tile[(r  )*TSTR + col]     = acc[mt][nt][0] + bv.x;
            tile[(r  )*TSTR + col + 1] = acc[mt][nt][1] + bv.y;
            tile[(r+8)*TSTR + col]     = acc[mt][nt][2] + bv.x;
            tile[(r+8)*TSTR + col + 1] = acc[mt][nt][3] + bv.y;
        }
    }
    __syncthreads();

    const int bb    = bm >> 11;          // batch
    const int sbase = bm & 2047;

    if (bn < DMODEL) {
        // ---- Q region: rope + 1/sqrt(HD), -> q[b,h,s,d] ----
        const int h = bn >> 7;
        __half* dst = Qo + ((size_t)(bb*NHEADS + h))*SEQ*HDIM;
        const float scale = 0.08838834764831845f;
        for (int r = wid; r < 128; r += 8) {
            int s = sbase + r;
            float pos = (float)seq_pos[bb*SEQ + s];
            __half* d = dst + (size_t)s*HDIM;
            #pragma unroll
            for (int ii = 0; ii < 2; ii++) {
                int i = lane + ii*32;
                float frac = (float)(2*i) * (1.0f/128.0f);
                float ts = powf(10000.0f, frac);
                float sv, cv; sincosf(pos/ts, &sv, &cv);
                float x1 = tile[r*TSTR + i], x2 = tile[r*TSTR + i + 64];
                d[i]      = __float2half_rn((x1*cv - x2*sv) * scale);
                d[i + 64] = __float2half_rn((x2*cv + x1*sv) * scale);
            }
        }
    } else {
        const int off = bn - DMODEL;
        const int kv  = off >> 8;
        if (((off >> 7) & 1) == 0) {
            // ---- K region: rope -> k[b,kv,s,d] ----
            __half* dst = Ko + ((size_t)(bb*NKV + kv))*SEQ*HDIM;
            for (int r = wid; r < 128; r += 8) {
                int s = sbase + r;
                float pos = (float)seq_pos[bb*SEQ + s];
                __half* d = dst + (size_t)s*HDIM;
                #pragma unroll
                for (int ii = 0; ii < 2; ii++) {
                    int i = lane + ii*32;
                    float frac = (float)(2*i) * (1.0f/128.0f);
                    float ts = powf(10000.0f, frac);
                    float sv, cv; sincosf(pos/ts, &sv, &cv);
                    float x1 = tile[r*TSTR + i], x2 = tile[r*TSTR + i + 64];
                    d[i]      = __float2half_rn(x1*cv - x2*sv);
                    d[i + 64] = __float2half_rn(x2*cv + x1*sv);
                }
            }
        } else {
            // ---- V region: transpose -> vt[b,kv,d,s] ----
            __half* dst = Vt + ((size_t)(bb*NKV + kv))*HDIM*SEQ;
            #pragma unroll
            for (int ci = 0; ci < 16; ci++) {
                int c = wid*16 + ci;
                __half* dc = dst + (size_t)c*SEQ + sbase;
                #pragma unroll
                for (int rr = 0; rr < 4; rr++) {
                    int r = lane + rr*32;
                    dc[r] = __float2half_rn(tile[r*TSTR + c]);
                }
            }
        }
    }
}

// ---------------------------------------------------------------------------
// fp16 GEMM (fp32 accum): C[M,N] = A[M,K] @ B[N,K]^T + bias  (O projection)
// ---------------------------------------------------------------------------
__global__ __launch_bounds__(256, 2) void gemm_f16(
    const __half* __restrict__ A, const __half* __restrict__ B,
    const float* __restrict__ bias, float* __restrict__ C,
    int M, int N, int K)
{
    extern __shared__ __half sh[];
    const int tid  = threadIdx.x;
    const int lane = tid & 31, wid = tid >> 5;
    const int wr   = wid >> 2, wc = wid & 3;
    const int gr   = lane >> 2, qd = lane & 3;
    const int bm   = blockIdx.y*128, bn = blockIdx.x*128;

    float acc[4][4][4];
    #pragma unroll
    for (int i = 0; i < 4; i++)
        #pragma unroll
        for (int j = 0; j < 4; j++)
            #pragma unroll
            for (int r = 0; r < 4; r++) acc[i][j][r] = 0.f;

    auto load_tile = [&](int buf, int k0) {
        __half* sA = sh + buf*HBUF;
        __half* sB = sA + 128*HSTR;
        #pragma unroll
        for (int i = 0; i < 4; i++) {
            int slot = tid + i*256;
            int r = slot >> 3, c8 = (slot & 7)*8;
            cpa16(sA + r*HSTR + c8, A + (size_t)(bm + r)*K + k0 + c8);
            cpa16(sB + r*HSTR + c8, B + (size_t)(bn + r)*K + k0 + c8);
        }
        cp_commit();
    };

    load_tile(0, 0);

    const int KT = K / 64;
    int buf = 0;
    for (int it = 0; it < KT; it++) {
        if (it + 1 < KT) { load_tile(buf ^ 1, (it + 1)*64); cp_wait1(); }
        else             { cp_wait0(); }
        __syncthreads();

        const __half* sA = sh + buf*HBUF;
        const __half* sB = sA + 128*HSTR;

        #pragma unroll
        for (int ks = 0; ks < 4; ks++) {
            const int k = ks*16;
            uint32_t a[4][4], b[4][2];
            #pragma unroll
            for (int mt = 0; mt < 4; mt++) {
                int r = wr*64 + mt*16 + gr;
                a[mt][0] = *(const uint32_t*)(sA + (r  )*HSTR + k     + 2*qd);
                a[mt][1] = *(const uint32_t*)(sA + (r+8)*HSTR + k     + 2*qd);
                a[mt][2] = *(const uint32_t*)(sA + (r  )*HSTR + k + 8 + 2*qd);
                a[mt][3] = *(const uint32_t*)(sA + (r+8)*HSTR + k + 8 + 2*qd);
            }
            #pragma unroll
            for (int nt = 0; nt < 4; nt++) {
                int n = wc*32 + nt*8 + gr;
                b[nt][0] = *(const uint32_t*)(sB + n*HSTR + k     + 2*qd);
                b[nt][1] = *(const uint32_t*)(sB + n*HSTR + k + 8 + 2*qd);
            }
            #pragma unroll
            for (int mt = 0; mt < 4; mt++)
                #pragma unroll
                for (int nt = 0; nt < 4; nt++)
                    mma_f16(acc[mt][nt], a[mt], b[nt]);
        }
        __syncthreads();
        buf ^= 1;
    }

    #pragma unroll
    for (int nt = 0; nt < 4; nt++) {
        int col = bn + wc*32 + nt*8 + 2*qd;
        float2 bv = *(const float2*)(bias + col);
        #pragma unroll
        for (int mt = 0; mt < 4; mt++) {
            int row = bm + wr*64 + mt*16 + gr;
            *(float2*)(C + (size_t)row*N + col) =
                make_float2(acc[mt][nt][0] + bv.x, acc[mt][nt][1] + bv.y);
            *(float2*)(C + (size_t)(row + 8)*N + col) =
                make_float2(acc[mt][nt][2] + bv.x, acc[mt][nt][3] + bv.y);
        }
    }
}

// ---------------------------------------------------------------------------
// Flash attention, fp16 HMMA, causal, GQA. 256 thr = 8 warps, occ 2.
// ---------------------------------------------------------------------------
#define QS 136
#define VS 72
#define PS 72
#define SMH_Q   0
#define SMH_K0  (64*QS)
#define SMH_K1  (SMH_K0 + 64*QS)
#define SMH_V0  (SMH_K1 + 64*QS)
#define SMH_V1  (SMH_V0 + 128*VS)
#define SMH_P   (SMH_V1 + 128*VS)
#define SMH_TOT (SMH_P + 64*PS)
#define FLASH_SMEM (SMH_TOT*2 + 1024)

__global__ __launch_bounds__(256, 2) void flash_f16(
    const __half* __restrict__ Q, const __half* __restrict__ Kg,
    const __half* __restrict__ Vtg, __half* __restrict__ X)
{
    extern __shared__ __half smh[];
    float* redm = (float*)(smh + SMH_TOT);
    float* reds = redm + 128;

    const int qt  = 31 - blockIdx.x;
    const int h   = blockIdx.y;
    const int b   = blockIdx.z;
    const int kvh = h >> 2;
    const int q0  = qt * 64;

    const int tid  = threadIdx.x;
    const int lane = tid & 31, wid = tid >> 5;
    const int wr   = wid >> 1, wc = wid & 1;
    const int gr   = lane >> 2, qd = lane & 3;
    const int r0   = wr*16 + gr, r1 = r0 + 8;

    const __half* qb  = Q   + ((size_t)(b*NHEADS + h)*SEQ + q0)*HDIM;
    const __half* kb  = Kg  + (size_t)(b*NKV + kvh)*SEQ*HDIM;
    const __half* vtb = Vtg + (size_t)(b*NKV + kvh)*HDIM*SEQ;

    auto load_kv = [&](int buf, int kt) {
        __half* Ks = smh + (buf ? SMH_K1 : SMH_K0);
        __half* Vs = smh + (buf ? SMH_V1 : SMH_V0);
        const __half* kp = kb + (size_t)kt*64*HDIM;
        #pragma unroll
        for (int i = 0; i < 4; i++) {
            int slot = tid + i*256;
            int r = slot >> 4, c8 = (slot & 15)*8;
            cpa16(Ks + r*QS + c8, kp + r*HDIM + c8);
        }
        #pragma unroll
        for (int i = 0; i < 4; i++) {
            int slot = tid + i*256;
            int d = slot >> 3, c8 = (slot & 7)*8;
            cpa16(Vs + d*VS + c8, vtb + (size_t)d*SEQ + kt*64 + c8);
        }
        cp_commit();
    };

    #pragma unroll
    for (int i = 0; i < 4; i++) {
        int slot = tid + i*256;
        int r = slot >> 4, c8 = (slot & 15)*8;
        cpa16(smh + SMH_Q + r*QS + c8, qb + r*HDIM + c8);
    }
    load_kv(0, 0);

    float o[8][4];
    #pragma unroll
    for (int i = 0; i < 8; i++)
        #pragma unroll
        for (int j = 0; j < 4; j++) o[i][j] = 0.f;
    float m0 = -INFINITY, m1 = -INFINITY, l0 = 0.f, l1 = 0.f;

    const __half* Qs = smh + SMH_Q;
    __half* Ps = smh + SMH_P;

    for (int kt = 0; kt <= qt; kt++) {
        const int buf = kt & 1;
        __syncthreads();
        if (kt < qt) { load_kv(buf ^ 1, kt + 1); cp_wait1(); }
        else         { cp_wait0(); }
        __syncthreads();

        const __half* Ks = smh + (buf ? SMH_K1 : SMH_K0);
        const __half* Vs = smh + (buf ? SMH_V1 : SMH_V0);

        float s[4][4];
        #pragma unroll
        for (int nt = 0; nt < 4; nt++)
            #pragma unroll
            for (int j = 0; j < 4; j++) s[nt][j] = 0.f;

        #pragma unroll
        for (int ks = 0; ks < 8; ks++) {
            const int k = ks*16;
            uint32_t a[4];
            a[0] = *(const uint32_t*)(Qs + r0*QS + k     + 2*qd);
            a[1] = *(const uint32_t*)(Qs + r1*QS + k     + 2*qd);
            a[2] = *(const uint32_t*)(Qs + r0*QS + k + 8 + 2*qd);
            a[3] = *(const uint32_t*)(Qs + r1*QS + k + 8 + 2*qd);
            #pragma unroll
            for (int nt = 0; nt < 4; nt++) {
                int cn = wc*32 + nt*8 + gr;
                uint32_t bf[2];
                bf[0] = *(const uint32_t*)(Ks + cn*QS + k     + 2*qd);
                bf[1] = *(const uint32_t*)(Ks + cn*QS + k + 8 + 2*qd);
                mma_f16(s[nt], a, bf);
            }
        }

        if (kt == qt) {
            #pragma unroll
            for (int nt = 0; nt < 4; nt++) {
                int cg = kt*64 + wc*32 + nt*8 + 2*qd;
                if (cg     > q0 + r0) s[nt][0] = -1e30f;
                if (cg + 1 > q0 + r0) s[nt][1] = -1e30f;
                if (cg     > q0 + r1) s[nt][2] = -1e30f;
                if (cg + 1 > q0 + r1) s[nt][3] = -1e30f;
            }
        }

        float mx0 = -INFINITY, mx1 = -INFINITY;
        #pragma unroll
        for (int nt = 0; nt < 4; nt++) {
            mx0 = fmaxf(mx0, fmaxf(s[nt][0], s[nt][1]));
            mx1 = fmaxf(mx1, fmaxf(s[nt][2], s[nt][3]));
        }
        mx0 = fmaxf(mx0, __shfl_xor_sync(0xffffffffu, mx0, 1));
        mx0 = fmaxf(mx0, __shfl_xor_sync(0xffffffffu, mx0, 2));
        mx1 = fmaxf(mx1, __shfl_xor_sync(0xffffffffu, mx1, 1));
        mx1 = fmaxf(mx1, __shfl_xor_sync(0xffffffffu, mx1, 2));
        if (qd == 0) { redm[wc*64 + r0] = mx0; redm[wc*64 + r1] = mx1; }
        __syncthreads();
        float nm0 = fmaxf(m0, fmaxf(mx0, redm[(wc ^ 1)*64 + r0]));
        float nm1 = fmaxf(m1, fmaxf(mx1, redm[(wc ^ 1)*64 + r1]));
        float corr0 = __expf(m0 - nm0), corr1 = __expf(m1 - nm1);

        float sum0 = 0.f, sum1 = 0.f;
        #pragma unroll
        for (int nt = 0; nt < 4; nt++) {
            float p0 = __expf(s[nt][0] - nm0);
            float p1 = __expf(s[nt][1] - nm0);
            float p2 = __expf(s[nt][2] - nm1);
            float p3 = __expf(s[nt][3] - nm1);
            sum0 += p0 + p1; sum1 += p2 + p3;
            int cc = wc*32 + nt*8 + 2*qd;
            *(__half2*)(Ps + r0*PS + cc) = __floats2half2_rn(p0, p1);
            *(__half2*)(Ps + r1*PS + cc) = __floats2half2_rn(p2, p3);
        }
        sum0 += __shfl_xor_sync(0xffffffffu, sum0, 1);
        sum0 += __shfl_xor_sync(0xffffffffu, sum0, 2);
        sum1 += __shfl_xor_sync(0xffffffffu, sum1, 1);
        sum1 += __shfl_xor_sync(0xffffffffu, sum1, 2);
        if (qd == 0) { reds[wc*64 + r0] = sum0; reds[wc*64 + r1] = sum1; }
        __syncthreads();
        l0 = l0*corr0 + sum0 + reds[(wc ^ 1)*64 + r0];
        l1 = l1*corr1 + sum1 + reds[(wc ^ 1)*64 + r1];
        m0 = nm0; m1 = nm1;

        #pragma unroll
        for (int nt = 0; nt < 8; nt++) {
            o[nt][0] *= corr0; o[nt][1] *= corr0;
            o[nt][2] *= corr1; o[nt][3] *= corr1;
        }

        #pragma unroll
        for (int ks = 0; ks < 4; ks++) {
            const int k = ks*16;
            uint32_t a[4];
            a[0] = *(const uint32_t*)(Ps + r0*PS + k     + 2*qd);
            a[1] = *(const uint32_t*)(Ps + r1*PS + k     + 2*qd);
            a[2] = *(const uint32_t*)(Ps + r0*PS + k + 8 + 2*qd);
            a[3] = *(const uint32_t*)(Ps + r1*PS + k + 8 + 2*qd);
            #pragma unroll
            for (int nt = 0; nt < 8; nt++) {
                int cn = wc*64 + nt*8 + gr;
                uint32_t bf[2];
                bf[0] = *(const uint32_t*)(Vs + cn*VS + k     + 2*qd);
                bf[1] = *(const uint32_t*)(Vs + cn*VS + k + 8 + 2*qd);
                mma_f16(o[nt], a, bf);
            }
        }
    }

    float inv0 = 1.f / l0, inv1 = 1.f / l1;
    size_t rb0 = ((size_t)(b*SEQ + q0 + r0))*DMODEL + h*HDIM;
    size_t rb1 = ((size_t)(b*SEQ + q0 + r1))*DMODEL + h*HDIM;
    #pragma unroll
    for (int nt = 0; nt < 8; nt++) {
        int cc = wc*64 + nt*8 + 2*qd;
        *(__half2*)(X + rb0 + cc) = __floats2half2_rn(o[nt][0]*inv0, o[nt][1]*inv0);
        *(__half2*)(X + rb1 + cc) = __floats2half2_rn(o[nt][2]*inv1, o[nt][3]*inv1);
    }
}

// ---------------------------------------------------------------------------
// Launch
// ---------------------------------------------------------------------------
extern "C" void kernel_launch(void* const* d_in, const int* in_sizes, int n_in,
                              void* d_out, int out_size)
{
    const float* inputs  = (const float*)d_in[0];
    const int*   seq_pos = (const int*)  d_in[1];
    const float* wq      = (const float*)d_in[2];
    const float* bq      = (const float*)d_in[3];
    const float* wkv     = (const float*)d_in[4];
    const float* bkv     = (const float*)d_in[5];
    const float* wo      = (const float*)d_in[6];
    const float* bo      = (const float*)d_in[7];
    float* out = (float*)d_out;

    __half *in_h, *wqkv_h, *wo_h, *x_h, *q, *k, *vt;
    cudaGetSymbolAddress((void**)&in_h,   g_in_h);
    cudaGetSymbolAddress((void**)&wqkv_h, g_wqkv_h);
    cudaGetSymbolAddress((void**)&wo_h,   g_wo_h);
    cudaGetSymbolAddress((void**)&x_h,    g_x_h);
    cudaGetSymbolAddress((void**)&q,      g_q);
    cudaGetSymbolAddress((void**)&k,      g_k);
    cudaGetSymbolAddress((void**)&vt,     g_vt);

    const int GEMM_SMEM = 2*HBUF*2;     // 73728 B
    cudaFuncSetAttribute(gemm_qkv,
                         cudaFuncAttributeMaxDynamicSharedMemorySize, GEMM_SMEM);
    cudaFuncSetAttribute(gemm_f16,
                         cudaFuncAttributeMaxDynamicSharedMemorySize, GEMM_SMEM);
    cudaFuncSetAttribute(flash_f16,
                         cudaFuncAttributeMaxDynamicSharedMemorySize, FLASH_SMEM);

    // 0) staging: inputs -> fp16; weights -> transposed fp16 (wq+wkv stacked)
    cvt_f16<<<(M_TOK*DMODEL/4)/256, 256>>>((const float4*)inputs,
        (__half2*)in_h, M_TOK*DMODEL/4);
    tcvt_f16<<<dim3(DMODEL/32, DMODEL/32), dim3(32,8)>>>(wq,  wqkv_h, DMODEL, DMODEL);
    tcvt_f16<<<dim3(KVDIM/32,  DMODEL/32), dim3(32,8)>>>(wkv, wqkv_h + (size_t)DMODEL*DMODEL,
                                                          DMODEL, KVDIM);
    tcvt_f16<<<dim3(DMODEL/32, DMODEL/32), dim3(32,8)>>>(wo,  wo_h, DMODEL, DMODEL);

    // 1) fused QKV projection + rope + V transpose
    gemm_qkv<<<dim3(NQKV/128, M_TOK/128), 256, GEMM_SMEM>>>(
        in_h, wqkv_h, bq, bkv, seq_pos, q, k, vt);

    // 2) flash attention (fp16 HMMA)
    flash_f16<<<dim3(SEQ/64, NHEADS, BATCH), 256, FLASH_SMEM>>>(q, k, vt, x_h);

    // 3) output projection
    gemm_f16<<<dim3(DMODEL/128, M_TOK/128), 256, GEMM_SMEM>>>(
        x_h, wo_h, bo, out, M_TOK, DMODEL, DMODEL);
}

// round 7
// speedup vs baseline: 5.8519x; 1.0315x over previous
#include <cuda_runtime.h>
#include <cuda_fp16.h>
#include <math.h>
#include <stdint.h>

// ---------------------------------------------------------------------------
// Problem constants
// ---------------------------------------------------------------------------
#define BATCH    2
#define SEQ      2048
#define DMODEL   2048
#define NHEADS   16
#define NKV      4
#define HDIM     128
#define M_TOK    (BATCH*SEQ)           // 4096
#define KVDIM    (NKV*2*HDIM)          // 1024
#define NQKV     (DMODEL + KVDIM)      // 3072

// ---------------------------------------------------------------------------
// Scratch
// ---------------------------------------------------------------------------
__device__ __half g_in_h  [M_TOK*DMODEL];
__device__ __half g_wqkv_h[NQKV*DMODEL];     // transposed [N,K]
__device__ __half g_wo_h  [DMODEL*DMODEL];   // transposed [N,K]
__device__ __half g_x_h   [M_TOK*DMODEL];    // attention out, fp16
__device__ __half g_q [BATCH*NHEADS*SEQ*HDIM];  // fp16 [B,H,S,D]
__device__ __half g_k [BATCH*NKV*SEQ*HDIM];     // fp16 [B,KV,S,D]
__device__ __half g_vt[BATCH*NKV*HDIM*SEQ];     // fp16 [B,KV,D,S]

// ---------------------------------------------------------------------------
// Helpers
// ---------------------------------------------------------------------------
__device__ __forceinline__ void mma_f16(float c[4], const uint32_t a[4], const uint32_t b[2]) {
    asm volatile(
        "mma.sync.aligned.m16n8k16.row.col.f32.f16.f16.f32 "
        "{%0,%1,%2,%3},{%4,%5,%6,%7},{%8,%9},{%0,%1,%2,%3};"
        : "+f"(c[0]), "+f"(c[1]), "+f"(c[2]), "+f"(c[3])
        : "r"(a[0]), "r"(a[1]), "r"(a[2]), "r"(a[3]), "r"(b[0]), "r"(b[1]));
}

__device__ __forceinline__ void cpa16(void* smem, const void* g) {
    uint32_t s = (uint32_t)__cvta_generic_to_shared(smem);
    asm volatile("cp.async.cg.shared.global [%0], [%1], 16;\n" :: "r"(s), "l"(g));
}
__device__ __forceinline__ void cp_commit() { asm volatile("cp.async.commit_group;"); }
__device__ __forceinline__ void cp_wait1()  { asm volatile("cp.async.wait_group 1;"); }
__device__ __forceinline__ void cp_wait0()  { asm volatile("cp.async.wait_group 0;"); }

__device__ __forceinline__ uint32_t packh2(float a, float b) {
    __half2 h = __floats2half2_rn(a, b);
    return *(uint32_t*)&h;
}

// ---------------------------------------------------------------------------
// Staging: fp32 -> fp16 (same layout)
// ---------------------------------------------------------------------------
__global__ void cvt_f16(const float4* __restrict__ src, __half2* __restrict__ dst, int n4)
{
    int i = blockIdx.x*blockDim.x + threadIdx.x;
    if (i >= n4) return;
    float4 x = src[i];
    dst[2*i]   = __floats2half2_rn(x.x, x.y);
    dst[2*i+1] = __floats2half2_rn(x.z, x.w);
}

// ---------------------------------------------------------------------------
// Staging: W[K,N] fp32 -> transposed fp16 [N,K]
// ---------------------------------------------------------------------------
__global__ void tcvt_f16(const float* __restrict__ W, __half* __restrict__ T, int K, int N)
{
    __shared__ float t[32][33];
    int n0 = blockIdx.x*32, k0 = blockIdx.y*32;
    int tx = threadIdx.x, ty = threadIdx.y;  // 32 x 8
    #pragma unroll
    for (int i = 0; i < 4; i++)
        t[ty + 8*i][tx] = W[(size_t)(k0 + ty + 8*i)*N + n0 + tx];
    __syncthreads();
    #pragma unroll
    for (int i = 0; i < 4; i++)
        T[(size_t)(n0 + ty + 8*i)*K + k0 + tx] = __float2half_rn(t[tx][ty + 8*i]);
}

// ---------------------------------------------------------------------------
// GEMM tile params
// ---------------------------------------------------------------------------
#define HSTR 72
#define HBUF 18432
#define TSTR 132

// ---------------------------------------------------------------------------
// Fused QKV projection + rope Q/K + transpose V (unchanged from R6)
// ---------------------------------------------------------------------------
__global__ __launch_bounds__(256, 2) void gemm_qkv(
    const __half* __restrict__ A, const __half* __restrict__ B,
    const float* __restrict__ bq, const float* __restrict__ bkv,
    const int* __restrict__ seq_pos,
    __half* __restrict__ Qo, __half* __restrict__ Ko, __half* __restrict__ Vt)
{
    extern __shared__ __half sh[];
    const int tid  = threadIdx.x;
    const int lane = tid & 31, wid = tid >> 5;
    const int wr   = wid >> 2, wc = wid & 3;
    const int gr   = lane >> 2, qd = lane & 3;
    const int bm   = blockIdx.y*128, bn = blockIdx.x*128;
    const int K    = DMODEL;

    float acc[4][4][4];
    #pragma unroll
    for (int i = 0; i < 4; i++)
        #pragma unroll
        for (int j = 0; j < 4; j++)
            #pragma unroll
            for (int r = 0; r < 4; r++) acc[i][j][r] = 0.f;

    auto load_tile = [&](int buf, int k0) {
        __half* sA = sh + buf*HBUF;
        __half* sB = sA + 128*HSTR;
        #pragma unroll
        for (int i = 0; i < 4; i++) {
            int slot = tid + i*256;
            int r = slot >> 3, c8 = (slot & 7)*8;
            cpa16(sA + r*HSTR + c8, A + (size_t)(bm + r)*K + k0 + c8);
            cpa16(sB + r*HSTR + c8, B + (size_t)(bn + r)*K + k0 + c8);
        }
        cp_commit();
    };

    load_tile(0, 0);

    const int KT = K / 64;
    int buf = 0;
    for (int it = 0; it < KT; it++) {
        if (it + 1 < KT) { load_tile(buf ^ 1, (it + 1)*64); cp_wait1(); }
        else             { cp_wait0(); }
        __syncthreads();

        const __half* sA = sh + buf*HBUF;
        const __half* sB = sA + 128*HSTR;

        #pragma unroll
        for (int ks = 0; ks < 4; ks++) {
            const int k = ks*16;
            uint32_t a[4][4], b[4][2];
            #pragma unroll
            for (int mt = 0; mt < 4; mt++) {
                int r = wr*64 + mt*16 + gr;
                a[mt][0] = *(const uint32_t*)(sA + (r  )*HSTR + k     + 2*qd);
                a[mt][1] = *(const uint32_t*)(sA + (r+8)*HSTR + k     + 2*qd);
                a[mt][2] = *(const uint32_t*)(sA + (r  )*HSTR + k + 8 + 2*qd);
                a[mt][3] = *(const uint32_t*)(sA + (r+8)*HSTR + k + 8 + 2*qd);
            }
            #pragma unroll
            for (int nt = 0; nt < 4; nt++) {
                int n = wc*32 + nt*8 + gr;
                b[nt][0] = *(const uint32_t*)(sB + n*HSTR + k     + 2*qd);
                b[nt][1] = *(const uint32_t*)(sB + n*HSTR + k + 8 + 2*qd);
            }
            #pragma unroll
            for (int mt = 0; mt < 4; mt++)
                #pragma unroll
                for (int nt = 0; nt < 4; nt++)
                    mma_f16(acc[mt][nt], a[mt], b[nt]);
        }
        __syncthreads();
        buf ^= 1;
    }

    float* tile = (float*)sh;
    const float* bias = (bn < DMODEL) ? (bq + bn) : (bkv + bn - DMODEL);
    #pragma unroll
    for (int nt = 0; nt < 4; nt++) {
        int col = wc*32 + nt*8 + 2*qd;
        float2 bv = *(const float2*)(bias + col);
        #pragma unroll
        for (int mt = 0; mt < 4; mt++) {
            int r = wr*64 + mt*16 + gr;
            tile[(r  )*TSTR + col]     = acc[mt][nt][0] + bv.x;
            tile[(r  )*TSTR + col + 1] = acc[mt][nt][1] + bv.y;
            tile[(r+8)*TSTR + col]     = acc[mt][nt][2] + bv.x;
            tile[(r+8)*TSTR + col + 1] = acc[mt][nt][3] + bv.y;
        }
    }
    __syncthreads();

    const int bb    = bm >> 11;
    const int sbase = bm & 2047;

    if (bn < DMODEL) {
        const int h = bn >> 7;
        __half* dst = Qo + ((size_t)(bb*NHEADS + h))*SEQ*HDIM;
        const float scale = 0.08838834764831845f;
        for (int r = wid; r < 128; r += 8) {
            int s = sbase + r;
            float pos = (float)seq_pos[bb*SEQ + s];
            __half* d = dst + (size_t)s*HDIM;
            #pragma unroll
            for (int ii = 0; ii < 2; ii++) {
                int i = lane + ii*32;
                float frac = (float)(2*i) * (1.0f/128.0f);
                float ts = powf(10000.0f, frac);
                float sv, cv; sincosf(pos/ts, &sv, &cv);
                float x1 = tile[r*TSTR + i], x2 = tile[r*TSTR + i + 64];
                d[i]      = __float2half_rn((x1*cv - x2*sv) * scale);
                d[i + 64] = __float2half_rn((x2*cv + x1*sv) * scale);
            }
        }
    } else {
        const int off = bn - DMODEL;
        const int kv  = off >> 8;
        if (((off >> 7) & 1) == 0) {
            __half* dst = Ko + ((size_t)(bb*NKV + kv))*SEQ*HDIM;
            for (int r = wid; r < 128; r += 8) {
                int s = sbase + r;
                float pos = (float)seq_pos[bb*SEQ + s];
                __half* d = dst + (size_t)s*HDIM;
                #pragma unroll
                for (int ii = 0; ii < 2; ii++) {
                    int i = lane + ii*32;
                    float frac = (float)(2*i) * (1.0f/128.0f);
                    float ts = powf(10000.0f, frac);
                    float sv, cv; sincosf(pos/ts, &sv, &cv);
                    float x1 = tile[r*TSTR + i], x2 = tile[r*TSTR + i + 64];
                    d[i]      = __float2half_rn(x1*cv - x2*sv);
                    d[i + 64] = __float2half_rn(x2*cv + x1*sv);
                }
            }
        } else {
            __half* dst = Vt + ((size_t)(bb*NKV + kv))*HDIM*SEQ;
            #pragma unroll
            for (int ci = 0; ci < 16; ci++) {
                int c = wid*16 + ci;
                __half* dc = dst + (size_t)c*SEQ + sbase;
                #pragma unroll
                for (int rr = 0; rr < 4; rr++) {
                    int r = lane + rr*32;
                    dc[r] = __float2half_rn(tile[r*TSTR + c]);
                }
            }
        }
    }
}

// ---------------------------------------------------------------------------
// O-projection GEMM (unchanged from R6)
// ---------------------------------------------------------------------------
__global__ __launch_bounds__(256, 2) void gemm_f16(
    const __half* __restrict__ A, const __half* __restrict__ B,
    const float* __restrict__ bias, float* __restrict__ C,
    int M, int N, int K)
{
    extern __shared__ __half sh[];
    const int tid  = threadIdx.x;
    const int lane = tid & 31, wid = tid >> 5;
    const int wr   = wid >> 2, wc = wid & 3;
    const int gr   = lane >> 2, qd = lane & 3;
    const int bm   = blockIdx.y*128, bn = blockIdx.x*128;

    float acc[4][4][4];
    #pragma unroll
    for (int i = 0; i < 4; i++)
        #pragma unroll
        for (int j = 0; j < 4; j++)
            #pragma unroll
            for (int r = 0; r < 4; r++) acc[i][j][r] = 0.f;

    auto load_tile = [&](int buf, int k0) {
        __half* sA = sh + buf*HBUF;
        __half* sB = sA + 128*HSTR;
        #pragma unroll
        for (int i = 0; i < 4; i++) {
            int slot = tid + i*256;
            int r = slot >> 3, c8 = (slot & 7)*8;
            cpa16(sA + r*HSTR + c8, A + (size_t)(bm + r)*K + k0 + c8);
            cpa16(sB + r*HSTR + c8, B + (size_t)(bn + r)*K + k0 + c8);
        }
        cp_commit();
    };

    load_tile(0, 0);

    const int KT = K / 64;
    int buf = 0;
    for (int it = 0; it < KT; it++) {
        if (it + 1 < KT) { load_tile(buf ^ 1, (it + 1)*64); cp_wait1(); }
        else             { cp_wait0(); }
        __syncthreads();

        const __half* sA = sh + buf*HBUF;
        const __half* sB = sA + 128*HSTR;

        #pragma unroll
        for (int ks = 0; ks < 4; ks++) {
            const int k = ks*16;
            uint32_t a[4][4], b[4][2];
            #pragma unroll
            for (int mt = 0; mt < 4; mt++) {
                int r = wr*64 + mt*16 + gr;
                a[mt][0] = *(const uint32_t*)(sA + (r  )*HSTR + k     + 2*qd);
                a[mt][1] = *(const uint32_t*)(sA + (r+8)*HSTR + k     + 2*qd);
                a[mt][2] = *(const uint32_t*)(sA + (r  )*HSTR + k + 8 + 2*qd);
                a[mt][3] = *(const uint32_t*)(sA + (r+8)*HSTR + k + 8 + 2*qd);
            }
            #pragma unroll
            for (int nt = 0; nt < 4; nt++) {
                int n = wc*32 + nt*8 + gr;
                b[nt][0] = *(const uint32_t*)(sB + n*HSTR + k     + 2*qd);
                b[nt][1] = *(const uint32_t*)(sB + n*HSTR + k + 8 + 2*qd);
            }
            #pragma unroll
            for (int mt = 0; mt < 4; mt++)
                #pragma unroll
                for (int nt = 0; nt < 4; nt++)
                    mma_f16(acc[mt][nt], a[mt], b[nt]);
        }
        __syncthreads();
        buf ^= 1;
    }

    #pragma unroll
    for (int nt = 0; nt < 4; nt++) {
        int col = bn + wc*32 + nt*8 + 2*qd;
        float2 bv = *(const float2*)(bias + col);
        #pragma unroll
        for (int mt = 0; mt < 4; mt++) {
            int row = bm + wr*64 + mt*16 + gr;
            *(float2*)(C + (size_t)row*N + col) =
                make_float2(acc[mt][nt][0] + bv.x, acc[mt][nt][1] + bv.y);
            *(float2*)(C + (size_t)(row + 8)*N + col) =
                make_float2(acc[mt][nt][2] + bv.x, acc[mt][nt][3] + bv.y);
        }
    }
}

// ---------------------------------------------------------------------------
// Flash attention v2: 128 thr = 4 warps, each warp owns 16 full rows.
// Q and P in registers (QK C-frag == PV A-frag layout), K/Vt double-buffered.
// Only 2 barriers per kt tile, no cross-warp reductions.
// ---------------------------------------------------------------------------
#define QS 136
#define VS 72
#define SMH_K0  0
#define SMH_K1  (64*QS)
#define SMH_V0  (2*64*QS)
#define SMH_V1  (2*64*QS + 128*VS)
#define FLASH_SMEM ((2*64*QS + 2*128*VS)*2)   // 71680 B

__global__ __launch_bounds__(128, 3) void flash_f16(
    const __half* __restrict__ Q, const __half* __restrict__ Kg,
    const __half* __restrict__ Vtg, __half* __restrict__ X)
{
    extern __shared__ __half smh[];

    const int qt  = 31 - blockIdx.x;
    const int h   = blockIdx.y;
    const int b   = blockIdx.z;
    const int kvh = h >> 2;
    const int q0  = qt * 64;

    const int tid  = threadIdx.x;
    const int lane = tid & 31, wid = tid >> 5;
    const int gr   = lane >> 2, qd = lane & 3;
    const int r0   = wid*16 + gr, r1 = r0 + 8;   // rows within q tile

    const __half* qb  = Q   + ((size_t)(b*NHEADS + h)*SEQ + q0)*HDIM;
    const __half* kb  = Kg  + (size_t)(b*NKV + kvh)*SEQ*HDIM;
    const __half* vtb = Vtg + (size_t)(b*NKV + kvh)*HDIM*SEQ;

    // ---- Q fragments in registers: 8 ksteps x 4 regs ----
    uint32_t qa[8][4];
    #pragma unroll
    for (int ks = 0; ks < 8; ks++) {
        qa[ks][0] = *(const uint32_t*)(qb + (size_t)r0*HDIM + ks*16     + 2*qd);
        qa[ks][1] = *(const uint32_t*)(qb + (size_t)r1*HDIM + ks*16     + 2*qd);
        qa[ks][2] = *(const uint32_t*)(qb + (size_t)r0*HDIM + ks*16 + 8 + 2*qd);
        qa[ks][3] = *(const uint32_t*)(qb + (size_t)r1*HDIM + ks*16 + 8 + 2*qd);
    }

    auto load_kv = [&](int buf, int kt) {
        __half* Ks = smh + (buf ? SMH_K1 : SMH_K0);
        __half* Vs = smh + (buf ? SMH_V1 : SMH_V0);
        const __half* kp = kb + (size_t)kt*64*HDIM;
        #pragma unroll
        for (int i = 0; i < 8; i++) {
            int slot = tid + i*128;
            int r = slot >> 4, c8 = (slot & 15)*8;
            cpa16(Ks + r*QS + c8, kp + r*HDIM + c8);
        }
        #pragma unroll
        for (int i = 0; i < 8; i++) {
            int slot = tid + i*128;
            int d = slot >> 3, c8 = (slot & 7)*8;
            cpa16(Vs + d*VS + c8, vtb + (size_t)d*SEQ + kt*64 + c8);
        }
        cp_commit();
    };

    load_kv(0, 0);

    float o[16][4];
    #pragma unroll
    for (int i = 0; i < 16; i++)
        #pragma unroll
        for (int j = 0; j < 4; j++) o[i][j] = 0.f;
    float m0 = -INFINITY, m1 = -INFINITY, l0 = 0.f, l1 = 0.f;

    for (int kt = 0; kt <= qt; kt++) {
        const int buf = kt & 1;
        __syncthreads();          // all warps done reading buf^1 (prev iter)
        if (kt < qt) { load_kv(buf ^ 1, kt + 1); cp_wait1(); }
        else         { cp_wait0(); }
        __syncthreads();          // buf data visible

        const __half* Ks = smh + (buf ? SMH_K1 : SMH_K0);
        const __half* Vs = smh + (buf ? SMH_V1 : SMH_V0);

        // ---- S = Q K^T : 16 rows x 64 cols per warp ----
        float s[8][4];
        #pragma unroll
        for (int nt = 0; nt < 8; nt++)
            #pragma unroll
            for (int j = 0; j < 4; j++) s[nt][j] = 0.f;

        #pragma unroll
        for (int ks = 0; ks < 8; ks++) {
            const int k = ks*16;
            #pragma unroll
            for (int nt = 0; nt < 8; nt++) {
                int cn = nt*8 + gr;
                uint32_t bf[2];
                bf[0] = *(const uint32_t*)(Ks + cn*QS + k     + 2*qd);
                bf[1] = *(const uint32_t*)(Ks + cn*QS + k + 8 + 2*qd);
                mma_f16(s[nt], qa[ks], bf);
            }
        }

        if (kt == qt) {
            #pragma unroll
            for (int nt = 0; nt < 8; nt++) {
                int cg = kt*64 + nt*8 + 2*qd;
                if (cg     > q0 + r0) s[nt][0] = -1e30f;
                if (cg + 1 > q0 + r0) s[nt][1] = -1e30f;
                if (cg     > q0 + r1) s[nt][2] = -1e30f;
                if (cg + 1 > q0 + r1) s[nt][3] = -1e30f;
            }
        }

        // ---- online softmax (quad shuffles only) ----
        float mx0 = -INFINITY, mx1 = -INFINITY;
        #pragma unroll
        for (int nt = 0; nt < 8; nt++) {
            mx0 = fmaxf(mx0, fmaxf(s[nt][0], s[nt][1]));
            mx1 = fmaxf(mx1, fmaxf(s[nt][2], s[nt][3]));
        }
        mx0 = fmaxf(mx0, __shfl_xor_sync(0xffffffffu, mx0, 1));
        mx0 = fmaxf(mx0, __shfl_xor_sync(0xffffffffu, mx0, 2));
        mx1 = fmaxf(mx1, __shfl_xor_sync(0xffffffffu, mx1, 1));
        mx1 = fmaxf(mx1, __shfl_xor_sync(0xffffffffu, mx1, 2));
        float nm0 = fmaxf(m0, mx0), nm1 = fmaxf(m1, mx1);
        float corr0 = __expf(m0 - nm0), corr1 = __expf(m1 - nm1);

        // exp + pack P into PV A-fragments (registers, no smem)
        uint32_t ph[8], pl[8];
        float sum0 = 0.f, sum1 = 0.f;
        #pragma unroll
        for (int nt = 0; nt < 8; nt++) {
            float p00 = __expf(s[nt][0] - nm0);
            float p01 = __expf(s[nt][1] - nm0);
            float p10 = __expf(s[nt][2] - nm1);
            float p11 = __expf(s[nt][3] - nm1);
            sum0 += p00 + p01; sum1 += p10 + p11;
            ph[nt] = packh2(p00, p01);
            pl[nt] = packh2(p10, p11);
        }
        sum0 += __shfl_xor_sync(0xffffffffu, sum0, 1);
        sum0 += __shfl_xor_sync(0xffffffffu, sum0, 2);
        sum1 += __shfl_xor_sync(0xffffffffu, sum1, 1);
        sum1 += __shfl_xor_sync(0xffffffffu, sum1, 2);
        l0 = l0*corr0 + sum0;
        l1 = l1*corr1 + sum1;
        m0 = nm0; m1 = nm1;

        #pragma unroll
        for (int nt = 0; nt < 16; nt++) {
            o[nt][0] *= corr0; o[nt][1] *= corr0;
            o[nt][2] *= corr1; o[nt][3] *= corr1;
        }

        // ---- O += P V : A-frag straight from ph/pl ----
        #pragma unroll
        for (int t = 0; t < 4; t++) {
            const int k = t*16;
            uint32_t a[4] = { ph[2*t], pl[2*t], ph[2*t + 1], pl[2*t + 1] };
            #pragma unroll
            for (int nt = 0; nt < 16; nt++) {
                int cn = nt*8 + gr;     // d index
                uint32_t bf[2];
                bf[0] = *(const uint32_t*)(Vs + cn*VS + k     + 2*qd);
                bf[1] = *(const uint32_t*)(Vs + cn*VS + k + 8 + 2*qd);
                mma_f16(o[nt], a, bf);
            }
        }
    }

    // ---- finalize, store fp16 [B,S,H*D] ----
    float inv0 = 1.f / l0, inv1 = 1.f / l1;
    size_t rb0 = ((size_t)(b*SEQ + q0 + r0))*DMODEL + h*HDIM;
    size_t rb1 = ((size_t)(b*SEQ + q0 + r1))*DMODEL + h*HDIM;
    #pragma unroll
    for (int nt = 0; nt < 16; nt++) {
        int cc = nt*8 + 2*qd;
        *(__half2*)(X + rb0 + cc) = __floats2half2_rn(o[nt][0]*inv0, o[nt][1]*inv0);
        *(__half2*)(X + rb1 + cc) = __floats2half2_rn(o[nt][2]*inv1, o[nt][3]*inv1);
    }
}

// ---------------------------------------------------------------------------
// Launch
// ---------------------------------------------------------------------------
extern "C" void kernel_launch(void* const* d_in, const int* in_sizes, int n_in,
                              void* d_out, int out_size)
{
    const float* inputs  = (const float*)d_in[0];
    const int*   seq_pos = (const int*)  d_in[1];
    const float* wq      = (const float*)d_in[2];
    const float* bq      = (const float*)d_in[3];
    const float* wkv     = (const float*)d_in[4];
    const float* bkv     = (const float*)d_in[5];
    const float* wo      = (const float*)d_in[6];
    const float* bo      = (const float*)d_in[7];
    float* out = (float*)d_out;

    __half *in_h, *wqkv_h, *wo_h, *x_h, *q, *k, *vt;
    cudaGetSymbolAddress((void**)&in_h,   g_in_h);
    cudaGetSymbolAddress((void**)&wqkv_h, g_wqkv_h);
    cudaGetSymbolAddress((void**)&wo_h,   g_wo_h);
    cudaGetSymbolAddress((void**)&x_h,    g_x_h);
    cudaGetSymbolAddress((void**)&q,      g_q);
    cudaGetSymbolAddress((void**)&k,      g_k);
    cudaGetSymbolAddress((void**)&vt,     g_vt);

    const int GEMM_SMEM = 2*HBUF*2;     // 73728 B
    cudaFuncSetAttribute(gemm_qkv,
                         cudaFuncAttributeMaxDynamicSharedMemorySize, GEMM_SMEM);
    cudaFuncSetAttribute(gemm_f16,
                         cudaFuncAttributeMaxDynamicSharedMemorySize, GEMM_SMEM);
    cudaFuncSetAttribute(flash_f16,
                         cudaFuncAttributeMaxDynamicSharedMemorySize, FLASH_SMEM);

    // 0) staging
    cvt_f16<<<(M_TOK*DMODEL/4)/256, 256>>>((const float4*)inputs,
        (__half2*)in_h, M_TOK*DMODEL/4);
    tcvt_f16<<<dim3(DMODEL/32, DMODEL/32), dim3(32,8)>>>(wq,  wqkv_h, DMODEL, DMODEL);
    tcvt_f16<<<dim3(KVDIM/32,  DMODEL/32), dim3(32,8)>>>(wkv, wqkv_h + (size_t)DMODEL*DMODEL,
                                                          DMODEL, KVDIM);
    tcvt_f16<<<dim3(DMODEL/32, DMODEL/32), dim3(32,8)>>>(wo,  wo_h, DMODEL, DMODEL);

    // 1) fused QKV projection + rope + V transpose
    gemm_qkv<<<dim3(NQKV/128, M_TOK/128), 256, GEMM_SMEM>>>(
        in_h, wqkv_h, bq, bkv, seq_pos, q, k, vt);

    // 2) flash attention (register-resident Q/P, 4 warps)
    flash_f16<<<dim3(SEQ/64, NHEADS, BATCH), 128, FLASH_SMEM>>>(q, k, vt, x_h);

    // 3) output projection
    gemm_f16<<<dim3(DMODEL/128, M_TOK/128), 256, GEMM_SMEM>>>(
        x_h, wo_h, bo, out, M_TOK, DMODEL, DMODEL);
}

// round 8
// speedup vs baseline: 5.9662x; 1.0195x over previous
#include <cuda_runtime.h>
#include <cuda_fp16.h>
#include <math.h>
#include <stdint.h>

// ---------------------------------------------------------------------------
// Problem constants
// ---------------------------------------------------------------------------
#define BATCH    2
#define SEQ      2048
#define DMODEL   2048
#define NHEADS   16
#define NKV      4
#define HDIM     128
#define M_TOK    (BATCH*SEQ)           // 4096
#define KVDIM    (NKV*2*HDIM)          // 1024
#define NQKV     (DMODEL + KVDIM)      // 3072

// ---------------------------------------------------------------------------
// Scratch
// ---------------------------------------------------------------------------
__device__ __half g_in_h  [M_TOK*DMODEL];
__device__ __half g_wqkv_h[NQKV*DMODEL];     // transposed [N,K]
__device__ __half g_wo_h  [DMODEL*DMODEL];   // transposed [N,K]
__device__ __half g_x_h   [M_TOK*DMODEL];    // attention out, fp16
__device__ __half g_q [BATCH*NHEADS*SEQ*HDIM];  // fp16 [B,H,S,D]
__device__ __half g_k [BATCH*NKV*SEQ*HDIM];     // fp16 [B,KV,S,D]
__device__ __half g_vt[BATCH*NKV*HDIM*SEQ];     // fp16 [B,KV,D,S]
__device__ float2 g_rope[SEQ*64];               // (sin, cos) per (pos, freq)

// ---------------------------------------------------------------------------
// Helpers
// ---------------------------------------------------------------------------
__device__ __forceinline__ void mma_f16(float c[4], const uint32_t a[4], const uint32_t b[2]) {
    asm volatile(
        "mma.sync.aligned.m16n8k16.row.col.f32.f16.f16.f32 "
        "{%0,%1,%2,%3},{%4,%5,%6,%7},{%8,%9},{%0,%1,%2,%3};"
        : "+f"(c[0]), "+f"(c[1]), "+f"(c[2]), "+f"(c[3])
        : "r"(a[0]), "r"(a[1]), "r"(a[2]), "r"(a[3]), "r"(b[0]), "r"(b[1]));
}

__device__ __forceinline__ void cpa16(void* smem, const void* g) {
    uint32_t s = (uint32_t)__cvta_generic_to_shared(smem);
    asm volatile("cp.async.cg.shared.global [%0], [%1], 16;\n" :: "r"(s), "l"(g));
}
__device__ __forceinline__ void cp_commit() { asm volatile("cp.async.commit_group;"); }
__device__ __forceinline__ void cp_wait1()  { asm volatile("cp.async.wait_group 1;"); }
__device__ __forceinline__ void cp_wait0()  { asm volatile("cp.async.wait_group 0;"); }

__device__ __forceinline__ uint32_t packh2(float a, float b) {
    __half2 h = __floats2half2_rn(a, b);
    return *(uint32_t*)&h;
}

// ---------------------------------------------------------------------------
// Merged staging kernel: one launch, 5 regions.
//  [0, 8192)              : inputs fp32 -> fp16
//  [8192, 12288)          : wq  transpose [2048x2048]
//  [12288, 14336)         : wkv transpose [2048x1024]
//  [14336, 18432)         : wo  transpose [2048x2048]
//  [18432, 18944)         : rope sin/cos table
// ---------------------------------------------------------------------------
#define STG_CVT   8192
#define STG_WQ    (STG_CVT + 4096)
#define STG_WKV   (STG_WQ + 2048)
#define STG_WO    (STG_WKV + 4096)
#define STG_TOT   (STG_WO + 512)

__device__ __forceinline__ void transpose32(const float* __restrict__ W,
                                            __half* __restrict__ T,
                                            int K, int N, int n0, int k0,
                                            int tid, float (*t)[33])
{
    int tx = tid & 31, ty = tid >> 5;   // 32 x 8
    #pragma unroll
    for (int i = 0; i < 4; i++)
        t[ty + 8*i][tx] = W[(size_t)(k0 + ty + 8*i)*N + n0 + tx];
    __syncthreads();
    #pragma unroll
    for (int i = 0; i < 4; i++)
        T[(size_t)(n0 + ty + 8*i)*K + k0 + tx] = __float2half_rn(t[tx][ty + 8*i]);
}

__global__ void staging(const float4* __restrict__ inputs,
                        const float* __restrict__ wq,
                        const float* __restrict__ wkv,
                        const float* __restrict__ wo,
                        __half2* __restrict__ in_h,
                        __half* __restrict__ wqkv_h,
                        __half* __restrict__ wo_h,
                        float2* __restrict__ rope)
{
    __shared__ float t[32][33];
    const int bid = blockIdx.x, tid = threadIdx.x;

    if (bid < STG_CVT) {
        int i = bid*256 + tid;
        float4 x = inputs[i];
        in_h[2*i]   = __floats2half2_rn(x.x, x.y);
        in_h[2*i+1] = __floats2half2_rn(x.z, x.w);
    } else if (bid < STG_WQ) {
        int b = bid - STG_CVT;               // 64 x 64 tiles
        transpose32(wq, wqkv_h, DMODEL, DMODEL, (b & 63)*32, (b >> 6)*32, tid, t);
    } else if (bid < STG_WKV) {
        int b = bid - STG_WQ;                // 32 x 64 tiles
        transpose32(wkv, wqkv_h + (size_t)DMODEL*DMODEL, DMODEL, KVDIM,
                    (b & 31)*32, (b >> 5)*32, tid, t);
    } else if (bid < STG_WO) {
        int b = bid - STG_WKV;
        transpose32(wo, wo_h, DMODEL, DMODEL, (b & 63)*32, (b >> 6)*32, tid, t);
    } else {
        int idx = (bid - STG_WO)*256 + tid;  // p*64 + i
        int p = idx >> 6, i = idx & 63;
        float frac = (float)(2*i) * (1.0f/128.0f);
        float ts   = powf(10000.0f, frac);
        float sv, cv; sincosf((float)p / ts, &sv, &cv);
        rope[idx] = make_float2(sv, cv);
    }
}

// ---------------------------------------------------------------------------
// GEMM tile params
// ---------------------------------------------------------------------------
#define HSTR 72
#define HBUF 18432
#define TSTR 132

// ---------------------------------------------------------------------------
// Fused QKV projection + rope Q/K (table-driven) + transpose V
// ---------------------------------------------------------------------------
__global__ __launch_bounds__(256, 2) void gemm_qkv(
    const __half* __restrict__ A, const __half* __restrict__ B,
    const float* __restrict__ bq, const float* __restrict__ bkv,
    const int* __restrict__ seq_pos, const float2* __restrict__ rope,
    __half* __restrict__ Qo, __half* __restrict__ Ko, __half* __restrict__ Vt)
{
    extern __shared__ __half sh[];
    const int tid  = threadIdx.x;
    const int lane = tid & 31, wid = tid >> 5;
    const int wr   = wid >> 2, wc = wid & 3;
    const int gr   = lane >> 2, qd = lane & 3;
    const int bm   = blockIdx.y*128, bn = blockIdx.x*128;
    const int K    = DMODEL;

    float acc[4][4][4];
    #pragma unroll
    for (int i = 0; i < 4; i++)
        #pragma unroll
        for (int j = 0; j < 4; j++)
            #pragma unroll
            for (int r = 0; r < 4; r++) acc[i][j][r] = 0.f;

    auto load_tile = [&](int buf, int k0) {
        __half* sA = sh + buf*HBUF;
        __half* sB = sA + 128*HSTR;
        #pragma unroll
        for (int i = 0; i < 4; i++) {
            int slot = tid + i*256;
            int r = slot >> 3, c8 = (slot & 7)*8;
            cpa16(sA + r*HSTR + c8, A + (size_t)(bm + r)*K + k0 + c8);
            cpa16(sB + r*HSTR + c8, B + (size_t)(bn + r)*K + k0 + c8);
        }
        cp_commit();
    };

    load_tile(0, 0);

    const int KT = K / 64;
    int buf = 0;
    for (int it = 0; it < KT; it++) {
        if (it + 1 < KT) { load_tile(buf ^ 1, (it + 1)*64); cp_wait1(); }
        else             { cp_wait0(); }
        __syncthreads();

        const __half* sA = sh + buf*HBUF;
        const __half* sB = sA + 128*HSTR;

        #pragma unroll
        for (int ks = 0; ks < 4; ks++) {
            const int k = ks*16;
            uint32_t a[4][4], b[4][2];
            #pragma unroll
            for (int mt = 0; mt < 4; mt++) {
                int r = wr*64 + mt*16 + gr;
                a[mt][0] = *(const uint32_t*)(sA + (r  )*HSTR + k     + 2*qd);
                a[mt][1] = *(const uint32_t*)(sA + (r+8)*HSTR + k     + 2*qd);
                a[mt][2] = *(const uint32_t*)(sA + (r  )*HSTR + k + 8 + 2*qd);
                a[mt][3] = *(const uint32_t*)(sA + (r+8)*HSTR + k + 8 + 2*qd);
            }
            #pragma unroll
            for (int nt = 0; nt < 4; nt++) {
                int n = wc*32 + nt*8 + gr;
                b[nt][0] = *(const uint32_t*)(sB + n*HSTR + k     + 2*qd);
                b[nt][1] = *(const uint32_t*)(sB + n*HSTR + k + 8 + 2*qd);
            }
            #pragma unroll
            for (int mt = 0; mt < 4; mt++)
                #pragma unroll
                for (int nt = 0; nt < 4; nt++)
                    mma_f16(acc[mt][nt], a[mt], b[nt]);
        }
        __syncthreads();
        buf ^= 1;
    }

    float* tile = (float*)sh;
    const float* bias = (bn < DMODEL) ? (bq + bn) : (bkv + bn - DMODEL);
    #pragma unroll
    for (int nt = 0; nt < 4; nt++) {
        int col = wc*32 + nt*8 + 2*qd;
        float2 bv = *(const float2*)(bias + col);
        #pragma unroll
        for (int mt = 0; mt < 4; mt++) {
            int r = wr*64 + mt*16 + gr;
            tile[(r  )*TSTR + col]     = acc[mt][nt][0] + bv.x;
            tile[(r  )*TSTR + col + 1] = acc[mt][nt][1] + bv.y;
            tile[(r+8)*TSTR + col]     = acc[mt][nt][2] + bv.x;
            tile[(r+8)*TSTR + col + 1] = acc[mt][nt][3] + bv.y;
        }
    }
    __syncthreads();

    const int bb    = bm >> 11;
    const int sbase = bm & 2047;

    if (bn < DMODEL) {
        const int h = bn >> 7;
        __half* dst = Qo + ((size_t)(bb*NHEADS + h))*SEQ*HDIM;
        const float scale = 0.08838834764831845f;
        for (int r = wid; r < 128; r += 8) {
            int s = sbase + r;
            int pos = seq_pos[bb*SEQ + s];
            __half* d = dst + (size_t)s*HDIM;
            #pragma unroll
            for (int ii = 0; ii < 2; ii++) {
                int i = lane + ii*32;
                float2 sc = rope[pos*64 + i];
                float x1 = tile[r*TSTR + i], x2 = tile[r*TSTR + i + 64];
                d[i]      = __float2half_rn((x1*sc.y - x2*sc.x) * scale);
                d[i + 64] = __float2half_rn((x2*sc.y + x1*sc.x) * scale);
            }
        }
    } else {
        const int off = bn - DMODEL;
        const int kv  = off >> 8;
        if (((off >> 7) & 1) == 0) {
            __half* dst = Ko + ((size_t)(bb*NKV + kv))*SEQ*HDIM;
            for (int r = wid; r < 128; r += 8) {
                int s = sbase + r;
                int pos = seq_pos[bb*SEQ + s];
                __half* d = dst + (size_t)s*HDIM;
                #pragma unroll
                for (int ii = 0; ii < 2; ii++) {
                    int i = lane + ii*32;
                    float2 sc = rope[pos*64 + i];
                    float x1 = tile[r*TSTR + i], x2 = tile[r*TSTR + i + 64];
                    d[i]      = __float2half_rn(x1*sc.y - x2*sc.x);
                    d[i + 64] = __float2half_rn(x2*sc.y + x1*sc.x);
                }
            }
        } else {
            __half* dst = Vt + ((size_t)(bb*NKV + kv))*HDIM*SEQ;
            #pragma unroll
            for (int ci = 0; ci < 16; ci++) {
                int c = wid*16 + ci;
                __half* dc = dst + (size_t)c*SEQ + sbase;
                #pragma unroll
                for (int rr = 0; rr < 4; rr++) {
                    int r = lane + rr*32;
                    dc[r] = __float2half_rn(tile[r*TSTR + c]);
                }
            }
        }
    }
}

// ---------------------------------------------------------------------------
// O-projection GEMM
// ---------------------------------------------------------------------------
__global__ __launch_bounds__(256, 2) void gemm_f16(
    const __half* __restrict__ A, const __half* __restrict__ B,
    const float* __restrict__ bias, float* __restrict__ C,
    int M, int N, int K)
{
    extern __shared__ __half sh[];
    const int tid  = threadIdx.x;
    const int lane = tid & 31, wid = tid >> 5;
    const int wr   = wid >> 2, wc = wid & 3;
    const int gr   = lane >> 2, qd = lane & 3;
    const int bm   = blockIdx.y*128, bn = blockIdx.x*128;

    float acc[4][4][4];
    #pragma unroll
    for (int i = 0; i < 4; i++)
        #pragma unroll
        for (int j = 0; j < 4; j++)
            #pragma unroll
            for (int r = 0; r < 4; r++) acc[i][j][r] = 0.f;

    auto load_tile = [&](int buf, int k0) {
        __half* sA = sh + buf*HBUF;
        __half* sB = sA + 128*HSTR;
        #pragma unroll
        for (int i = 0; i < 4; i++) {
            int slot = tid + i*256;
            int r = slot >> 3, c8 = (slot & 7)*8;
            cpa16(sA + r*HSTR + c8, A + (size_t)(bm + r)*K + k0 + c8);
            cpa16(sB + r*HSTR + c8, B + (size_t)(bn + r)*K + k0 + c8);
        }
        cp_commit();
    };

    load_tile(0, 0);

    const int KT = K / 64;
    int buf = 0;
    for (int it = 0; it < KT; it++) {
        if (it + 1 < KT) { load_tile(buf ^ 1, (it + 1)*64); cp_wait1(); }
        else             { cp_wait0(); }
        __syncthreads();

        const __half* sA = sh + buf*HBUF;
        const __half* sB = sA + 128*HSTR;

        #pragma unroll
        for (int ks = 0; ks < 4; ks++) {
            const int k = ks*16;
            uint32_t a[4][4], b[4][2];
            #pragma unroll
            for (int mt = 0; mt < 4; mt++) {
                int r = wr*64 + mt*16 + gr;
                a[mt][0] = *(const uint32_t*)(sA + (r  )*HSTR + k     + 2*qd);
                a[mt][1] = *(const uint32_t*)(sA + (r+8)*HSTR + k     + 2*qd);
                a[mt][2] = *(const uint32_t*)(sA + (r  )*HSTR + k + 8 + 2*qd);
                a[mt][3] = *(const uint32_t*)(sA + (r+8)*HSTR + k + 8 + 2*qd);
            }
            #pragma unroll
            for (int nt = 0; nt < 4; nt++) {
                int n = wc*32 + nt*8 + gr;
                b[nt][0] = *(const uint32_t*)(sB + n*HSTR + k     + 2*qd);
                b[nt][1] = *(const uint32_t*)(sB + n*HSTR + k + 8 + 2*qd);
            }
            #pragma unroll
            for (int mt = 0; mt < 4; mt++)
                #pragma unroll
                for (int nt = 0; nt < 4; nt++)
                    mma_f16(acc[mt][nt], a[mt], b[nt]);
        }
        __syncthreads();
        buf ^= 1;
    }

    #pragma unroll
    for (int nt = 0; nt < 4; nt++) {
        int col = bn + wc*32 + nt*8 + 2*qd;
        float2 bv = *(const float2*)(bias + col);
        #pragma unroll
        for (int mt = 0; mt < 4; mt++) {
            int row = bm + wr*64 + mt*16 + gr;
            *(float2*)(C + (size_t)row*N + col) =
                make_float2(acc[mt][nt][0] + bv.x, acc[mt][nt][1] + bv.y);
            *(float2*)(C + (size_t)(row + 8)*N + col) =
                make_float2(acc[mt][nt][2] + bv.x, acc[mt][nt][3] + bv.y);
        }
    }
}

// ---------------------------------------------------------------------------
// Flash attention: 128 thr = 4 warps, warp owns 16 full rows; Q/P in regs.
// ---------------------------------------------------------------------------
#define QS 136
#define VS 72
#define SMH_K0  0
#define SMH_K1  (64*QS)
#define SMH_V0  (2*64*QS)
#define SMH_V1  (2*64*QS + 128*VS)
#define FLASH_SMEM ((2*64*QS + 2*128*VS)*2)   // 71680 B

__global__ __launch_bounds__(128, 3) void flash_f16(
    const __half* __restrict__ Q, const __half* __restrict__ Kg,
    const __half* __restrict__ Vtg, __half* __restrict__ X)
{
    extern __shared__ __half smh[];

    const int qt  = 31 - blockIdx.x;
    const int h   = blockIdx.y;
    const int b   = blockIdx.z;
    const int kvh = h >> 2;
    const int q0  = qt * 64;

    const int tid  = threadIdx.x;
    const int lane = tid & 31, wid = tid >> 5;
    const int gr   = lane >> 2, qd = lane & 3;
    const int r0   = wid*16 + gr, r1 = r0 + 8;

    const __half* qb  = Q   + ((size_t)(b*NHEADS + h)*SEQ + q0)*HDIM;
    const __half* kb  = Kg  + (size_t)(b*NKV + kvh)*SEQ*HDIM;
    const __half* vtb = Vtg + (size_t)(b*NKV + kvh)*HDIM*SEQ;

    uint32_t qa[8][4];
    #pragma unroll
    for (int ks = 0; ks < 8; ks++) {
        qa[ks][0] = *(const uint32_t*)(qb + (size_t)r0*HDIM + ks*16     + 2*qd);
        qa[ks][1] = *(const uint32_t*)(qb + (size_t)r1*HDIM + ks*16     + 2*qd);
        qa[ks][2] = *(const uint32_t*)(qb + (size_t)r0*HDIM + ks*16 + 8 + 2*qd);
        qa[ks][3] = *(const uint32_t*)(qb + (size_t)r1*HDIM + ks*16 + 8 + 2*qd);
    }

    auto load_kv = [&](int buf, int kt) {
        __half* Ks = smh + (buf ? SMH_K1 : SMH_K0);
        __half* Vs = smh + (buf ? SMH_V1 : SMH_V0);
        const __half* kp = kb + (size_t)kt*64*HDIM;
        #pragma unroll
        for (int i = 0; i < 8; i++) {
            int slot = tid + i*128;
            int r = slot >> 4, c8 = (slot & 15)*8;
            cpa16(Ks + r*QS + c8, kp + r*HDIM + c8);
        }
        #pragma unroll
        for (int i = 0; i < 8; i++) {
            int slot = tid + i*128;
            int d = slot >> 3, c8 = (slot & 7)*8;
            cpa16(Vs + d*VS + c8, vtb + (size_t)d*SEQ + kt*64 + c8);
        }
        cp_commit();
    };

    load_kv(0, 0);

    float o[16][4];
    #pragma unroll
    for (int i = 0; i < 16; i++)
        #pragma unroll
        for (int j = 0; j < 4; j++) o[i][j] = 0.f;
    float m0 = -INFINITY, m1 = -INFINITY, l0 = 0.f, l1 = 0.f;

    for (int kt = 0; kt <= qt; kt++) {
        const int buf = kt & 1;
        __syncthreads();
        if (kt < qt) { load_kv(buf ^ 1, kt + 1); cp_wait1(); }
        else         { cp_wait0(); }
        __syncthreads();

        const __half* Ks = smh + (buf ? SMH_K1 : SMH_K0);
        const __half* Vs = smh + (buf ? SMH_V1 : SMH_V0);

        float s[8][4];
        #pragma unroll
        for (int nt = 0; nt < 8; nt++)
            #pragma unroll
            for (int j = 0; j < 4; j++) s[nt][j] = 0.f;

        #pragma unroll
        for (int ks = 0; ks < 8; ks++) {
            const int k = ks*16;
            #pragma unroll
            for (int nt = 0; nt < 8; nt++) {
                int cn = nt*8 + gr;
                uint32_t bf[2];
                bf[0] = *(const uint32_t*)(Ks + cn*QS + k     + 2*qd);
                bf[1] = *(const uint32_t*)(Ks + cn*QS + k + 8 + 2*qd);
                mma_f16(s[nt], qa[ks], bf);
            }
        }

        if (kt == qt) {
            #pragma unroll
            for (int nt = 0; nt < 8; nt++) {
                int cg = kt*64 + nt*8 + 2*qd;
                if (cg     > q0 + r0) s[nt][0] = -1e30f;
                if (cg + 1 > q0 + r0) s[nt][1] = -1e30f;
                if (cg     > q0 + r1) s[nt][2] = -1e30f;
                if (cg + 1 > q0 + r1) s[nt][3] = -1e30f;
            }
        }

        float mx0 = -INFINITY, mx1 = -INFINITY;
        #pragma unroll
        for (int nt = 0; nt < 8; nt++) {
            mx0 = fmaxf(mx0, fmaxf(s[nt][0], s[nt][1]));
            mx1 = fmaxf(mx1, fmaxf(s[nt][2], s[nt][3]));
        }
        mx0 = fmaxf(mx0, __shfl_xor_sync(0xffffffffu, mx0, 1));
        mx0 = fmaxf(mx0, __shfl_xor_sync(0xffffffffu, mx0, 2));
        mx1 = fmaxf(mx1, __shfl_xor_sync(0xffffffffu, mx1, 1));
        mx1 = fmaxf(mx1, __shfl_xor_sync(0xffffffffu, mx1, 2));
        float nm0 = fmaxf(m0, mx0), nm1 = fmaxf(m1, mx1);
        float corr0 = __expf(m0 - nm0), corr1 = __expf(m1 - nm1);

        uint32_t ph[8], pl[8];
        float sum0 = 0.f, sum1 = 0.f;
        #pragma unroll
        for (int nt = 0; nt < 8; nt++) {
            float p00 = __expf(s[nt][0] - nm0);
            float p01 = __expf(s[nt][1] - nm0);
            float p10 = __expf(s[nt][2] - nm1);
            float p11 = __expf(s[nt][3] - nm1);
            sum0 += p00 + p01; sum1 += p10 + p11;
            ph[nt] = packh2(p00, p01);
            pl[nt] = packh2(p10, p11);
        }
        sum0 += __shfl_xor_sync(0xffffffffu, sum0, 1);
        sum0 += __shfl_xor_sync(0xffffffffu, sum0, 2);
        sum1 += __shfl_xor_sync(0xffffffffu, sum1, 1);
        sum1 += __shfl_xor_sync(0xffffffffu, sum1, 2);
        l0 = l0*corr0 + sum0;
        l1 = l1*corr1 + sum1;
        m0 = nm0; m1 = nm1;

        #pragma unroll
        for (int nt = 0; nt < 16; nt++) {
            o[nt][0] *= corr0; o[nt][1] *= corr0;
            o[nt][2] *= corr1; o[nt][3] *= corr1;
        }

        #pragma unroll
        for (int t = 0; t < 4; t++) {
            const int k = t*16;
            uint32_t a[4] = { ph[2*t], pl[2*t], ph[2*t + 1], pl[2*t + 1] };
            #pragma unroll
            for (int nt = 0; nt < 16; nt++) {
                int cn = nt*8 + gr;
                uint32_t bf[2];
                bf[0] = *(const uint32_t*)(Vs + cn*VS + k     + 2*qd);
                bf[1] = *(const uint32_t*)(Vs + cn*VS + k + 8 + 2*qd);
                mma_f16(o[nt], a, bf);
            }
        }
    }

    float inv0 = 1.f / l0, inv1 = 1.f / l1;
    size_t rb0 = ((size_t)(b*SEQ + q0 + r0))*DMODEL + h*HDIM;
    size_t rb1 = ((size_t)(b*SEQ + q0 + r1))*DMODEL + h*HDIM;
    #pragma unroll
    for (int nt = 0; nt < 16; nt++) {
        int cc = nt*8 + 2*qd;
        *(__half2*)(X + rb0 + cc) = __floats2half2_rn(o[nt][0]*inv0, o[nt][1]*inv0);
        *(__half2*)(X + rb1 + cc) = __floats2half2_rn(o[nt][2]*inv1, o[nt][3]*inv1);
    }
}

// ---------------------------------------------------------------------------
// Launch
// ---------------------------------------------------------------------------
extern "C" void kernel_launch(void* const* d_in, const int* in_sizes, int n_in,
                              void* d_out, int out_size)
{
    const float* inputs  = (const float*)d_in[0];
    const int*   seq_pos = (const int*)  d_in[1];
    const float* wq      = (const float*)d_in[2];
    const float* bq      = (const float*)d_in[3];
    const float* wkv     = (const float*)d_in[4];
    const float* bkv     = (const float*)d_in[5];
    const float* wo      = (const float*)d_in[6];
    const float* bo      = (const float*)d_in[7];
    float* out = (float*)d_out;

    __half *in_h, *wqkv_h, *wo_h, *x_h, *q, *k, *vt;
    float2* rope;
    cudaGetSymbolAddress((void**)&in_h,   g_in_h);
    cudaGetSymbolAddress((void**)&wqkv_h, g_wqkv_h);
    cudaGetSymbolAddress((void**)&wo_h,   g_wo_h);
    cudaGetSymbolAddress((void**)&x_h,    g_x_h);
    cudaGetSymbolAddress((void**)&q,      g_q);
    cudaGetSymbolAddress((void**)&k,      g_k);
    cudaGetSymbolAddress((void**)&vt,     g_vt);
    cudaGetSymbolAddress((void**)&rope,   g_rope);

    const int GEMM_SMEM = 2*HBUF*2;     // 73728 B
    cudaFuncSetAttribute(gemm_qkv,
                         cudaFuncAttributeMaxDynamicSharedMemorySize, GEMM_SMEM);
    cudaFuncSetAttribute(gemm_f16,
                         cudaFuncAttributeMaxDynamicSharedMemorySize, GEMM_SMEM);
    cudaFuncSetAttribute(flash_f16,
                         cudaFuncAttributeMaxDynamicSharedMemorySize, FLASH_SMEM);

    // 0) merged staging (cvt + 3 transposes + rope table), one launch
    staging<<<STG_TOT, 256>>>((const float4*)inputs, wq, wkv, wo,
                              (__half2*)in_h, wqkv_h, wo_h, rope);

    // 1) fused QKV projection + rope + V transpose
    gemm_qkv<<<dim3(NQKV/128, M_TOK/128), 256, GEMM_SMEM>>>(
        in_h, wqkv_h, bq, bkv, seq_pos, rope, q, k, vt);

    // 2) flash attention
    flash_f16<<<dim3(SEQ/64, NHEADS, BATCH), 128, FLASH_SMEM>>>(q, k, vt, x_h);

    // 3) output projection
    gemm_f16<<<dim3(DMODEL/128, M_TOK/128), 256, GEMM_SMEM>>>(
        x_h, wo_h, bo, out, M_TOK, DMODEL, DMODEL);
}

// round 9
// speedup vs baseline: 6.5486x; 1.0976x over previous
#include <cuda_runtime.h>
#include <cuda_fp16.h>
#include <math.h>
#include <stdint.h>

// ---------------------------------------------------------------------------
// Problem constants
// ---------------------------------------------------------------------------
#define BATCH    2
#define SEQ      2048
#define DMODEL   2048
#define NHEADS   16
#define NKV      4
#define HDIM     128
#define M_TOK    (BATCH*SEQ)           // 4096
#define KVDIM    (NKV*2*HDIM)          // 1024
#define NQKV     (DMODEL + KVDIM)      // 3072

// ---------------------------------------------------------------------------
// Scratch
// ---------------------------------------------------------------------------
__device__ __half g_in_h  [M_TOK*DMODEL];
__device__ __half g_wqkv_h[NQKV*DMODEL];     // transposed [N,K]
__device__ __half g_wo_h  [DMODEL*DMODEL];   // transposed [N,K]
__device__ __half g_x_h   [M_TOK*DMODEL];    // attention out, fp16
__device__ __half g_q [BATCH*NHEADS*SEQ*HDIM];  // fp16 [B,H,S,D]
__device__ __half g_k [BATCH*NKV*SEQ*HDIM];     // fp16 [B,KV,S,D]
__device__ __half g_vt[BATCH*NKV*HDIM*SEQ];     // fp16 [B,KV,D,S]
__device__ float2 g_rope[SEQ*64];               // (sin, cos) per (pos, freq)

// ---------------------------------------------------------------------------
// Helpers
// ---------------------------------------------------------------------------
__device__ __forceinline__ void mma_f16(float c[4], const uint32_t a[4], const uint32_t b[2]) {
    asm volatile(
        "mma.sync.aligned.m16n8k16.row.col.f32.f16.f16.f32 "
        "{%0,%1,%2,%3},{%4,%5,%6,%7},{%8,%9},{%0,%1,%2,%3};"
        : "+f"(c[0]), "+f"(c[1]), "+f"(c[2]), "+f"(c[3])
        : "r"(a[0]), "r"(a[1]), "r"(a[2]), "r"(a[3]), "r"(b[0]), "r"(b[1]));
}

__device__ __forceinline__ void ldsm_x4(uint32_t r[4], uint32_t saddr) {
    asm volatile("ldmatrix.sync.aligned.m8n8.x4.shared.b16 {%0,%1,%2,%3}, [%4];"
        : "=r"(r[0]), "=r"(r[1]), "=r"(r[2]), "=r"(r[3]) : "r"(saddr));
}

__device__ __forceinline__ void cpa16(void* smem, const void* g) {
    uint32_t s = (uint32_t)__cvta_generic_to_shared(smem);
    asm volatile("cp.async.cg.shared.global [%0], [%1], 16;\n" :: "r"(s), "l"(g));
}
__device__ __forceinline__ void cp_commit() { asm volatile("cp.async.commit_group;"); }
__device__ __forceinline__ void cp_wait1()  { asm volatile("cp.async.wait_group 1;"); }
__device__ __forceinline__ void cp_wait0()  { asm volatile("cp.async.wait_group 0;"); }

__device__ __forceinline__ uint32_t packh2(float a, float b) {
    __half2 h = __floats2half2_rn(a, b);
    return *(uint32_t*)&h;
}

// ---------------------------------------------------------------------------
// Merged staging kernel (unchanged from R8)
// ---------------------------------------------------------------------------
#define STG_CVT   8192
#define STG_WQ    (STG_CVT + 4096)
#define STG_WKV   (STG_WQ + 2048)
#define STG_WO    (STG_WKV + 4096)
#define STG_TOT   (STG_WO + 512)

__device__ __forceinline__ void transpose32(const float* __restrict__ W,
                                            __half* __restrict__ T,
                                            int K, int N, int n0, int k0,
                                            int tid, float (*t)[33])
{
    int tx = tid & 31, ty = tid >> 5;
    #pragma unroll
    for (int i = 0; i < 4; i++)
        t[ty + 8*i][tx] = W[(size_t)(k0 + ty + 8*i)*N + n0 + tx];
    __syncthreads();
    #pragma unroll
    for (int i = 0; i < 4; i++)
        T[(size_t)(n0 + ty + 8*i)*K + k0 + tx] = __float2half_rn(t[tx][ty + 8*i]);
}

__global__ void staging(const float4* __restrict__ inputs,
                        const float* __restrict__ wq,
                        const float* __restrict__ wkv,
                        const float* __restrict__ wo,
                        __half2* __restrict__ in_h,
                        __half* __restrict__ wqkv_h,
                        __half* __restrict__ wo_h,
                        float2* __restrict__ rope)
{
    __shared__ float t[32][33];
    const int bid = blockIdx.x, tid = threadIdx.x;

    if (bid < STG_CVT) {
        int i = bid*256 + tid;
        float4 x = inputs[i];
        in_h[2*i]   = __floats2half2_rn(x.x, x.y);
        in_h[2*i+1] = __floats2half2_rn(x.z, x.w);
    } else if (bid < STG_WQ) {
        int b = bid - STG_CVT;
        transpose32(wq, wqkv_h, DMODEL, DMODEL, (b & 63)*32, (b >> 6)*32, tid, t);
    } else if (bid < STG_WKV) {
        int b = bid - STG_WQ;
        transpose32(wkv, wqkv_h + (size_t)DMODEL*DMODEL, DMODEL, KVDIM,
                    (b & 31)*32, (b >> 5)*32, tid, t);
    } else if (bid < STG_WO) {
        int b = bid - STG_WKV;
        transpose32(wo, wo_h, DMODEL, DMODEL, (b & 63)*32, (b >> 6)*32, tid, t);
    } else {
        int idx = (bid - STG_WO)*256 + tid;
        int p = idx >> 6, i = idx & 63;
        float frac = (float)(2*i) * (1.0f/128.0f);
        float ts   = powf(10000.0f, frac);
        float sv, cv; sincosf((float)p / ts, &sv, &cv);
        rope[idx] = make_float2(sv, cv);
    }
}

// ---------------------------------------------------------------------------
// GEMM tile params
// ---------------------------------------------------------------------------
#define HSTR 72
#define HBUF 18432
#define TSTR 132

// Shared GEMM mainloop (ldmatrix version) — emitted via macro to keep
// both gemm kernels identical.
// Requires: sh, tid, lane, wid, wr, wc, A, B, K, bm, bn, acc declared.
#define GEMM_MAINLOOP()                                                          \
    const uint32_t sb0 = (uint32_t)__cvta_generic_to_shared(sh);                 \
    const int rowA = (lane & 7) + ((lane >> 3) & 1)*8;                           \
    const int colA = (lane >> 4)*8;                                              \
    const int rowB = (lane & 7) + ((lane >> 4) << 3);                            \
    const int colB = ((lane >> 3) & 1)*8;                                        \
    const uint32_t aOff = ((wr*64 + rowA)*HSTR + colA)*2;                        \
    const uint32_t bOff = (128*HSTR + (wc*32 + rowB)*HSTR + colB)*2;             \
    auto load_tile = [&](int buf, int k0) {                                      \
        __half* sA = sh + buf*HBUF;                                              \
        __half* sB = sA + 128*HSTR;                                              \
        _Pragma("unroll")                                                        \
        for (int i = 0; i < 4; i++) {                                            \
            int slot = tid + i*256;                                              \
            int r = slot >> 3, c8 = (slot & 7)*8;                                \
            cpa16(sA + r*HSTR + c8, A + (size_t)(bm + r)*K + k0 + c8);           \
            cpa16(sB + r*HSTR + c8, B + (size_t)(bn + r)*K + k0 + c8);           \
        }                                                                        \
        cp_commit();                                                             \
    };                                                                           \
    load_tile(0, 0);                                                             \
    const int KT = K / 64;                                                       \
    int buf = 0;                                                                 \
    for (int it = 0; it < KT; it++) {                                            \
        if (it + 1 < KT) { load_tile(buf ^ 1, (it + 1)*64); cp_wait1(); }        \
        else             { cp_wait0(); }                                         \
        __syncthreads();                                                         \
        const uint32_t aBase = sb0 + buf*HBUF*2 + aOff;                          \
        const uint32_t bBase = sb0 + buf*HBUF*2 + bOff;                          \
        _Pragma("unroll")                                                        \
        for (int ks = 0; ks < 4; ks++) {                                         \
            uint32_t a[4][4], bp0[4], bp1[4];                                    \
            _Pragma("unroll")                                                    \
            for (int mt = 0; mt < 4; mt++)                                       \
                ldsm_x4(a[mt], aBase + (mt*16*HSTR + ks*16)*2);                  \
            ldsm_x4(bp0, bBase + ks*16*2);                                       \
            ldsm_x4(bp1, bBase + (16*HSTR + ks*16)*2);                           \
            _Pragma("unroll")                                                    \
            for (int mt = 0; mt < 4; mt++) {                                     \
                mma_f16(acc[mt][0], a[mt], bp0);                                 \
                mma_f16(acc[mt][1], a[mt], bp0 + 2);                             \
                mma_f16(acc[mt][2], a[mt], bp1);                                 \
                mma_f16(acc[mt][3], a[mt], bp1 + 2);                             \
            }                                                                    \
        }                                                                        \
        __syncthreads();                                                         \
        buf ^= 1;                                                                \
    }

// ---------------------------------------------------------------------------
// Fused QKV projection + rope Q/K (table) + transpose V
// ---------------------------------------------------------------------------
__global__ __launch_bounds__(256, 2) void gemm_qkv(
    const __half* __restrict__ A, const __half* __restrict__ B,
    const float* __restrict__ bq, const float* __restrict__ bkv,
    const int* __restrict__ seq_pos, const float2* __restrict__ rope,
    __half* __restrict__ Qo, __half* __restrict__ Ko, __half* __restrict__ Vt)
{
    extern __shared__ __half sh[];
    const int tid  = threadIdx.x;
    const int lane = tid & 31, wid = tid >> 5;
    const int wr   = wid >> 2, wc = wid & 3;
    const int gr   = lane >> 2, qd = lane & 3;
    const int bm   = blockIdx.y*128, bn = blockIdx.x*128;
    const int K    = DMODEL;

    float acc[4][4][4];
    #pragma unroll
    for (int i = 0; i < 4; i++)
        #pragma unroll
        for (int j = 0; j < 4; j++)
            #pragma unroll
            for (int r = 0; r < 4; r++) acc[i][j][r] = 0.f;

    GEMM_MAINLOOP()

    float* tile = (float*)sh;
    const float* bias = (bn < DMODEL) ? (bq + bn) : (bkv + bn - DMODEL);
    #pragma unroll
    for (int nt = 0; nt < 4; nt++) {
        int col = wc*32 + nt*8 + 2*qd;
        float2 bv = *(const float2*)(bias + col);
        #pragma unroll
        for (int mt = 0; mt < 4; mt++) {
            int r = wr*64 + mt*16 + gr;
            tile[(r  )*TSTR + col]     = acc[mt][nt][0] + bv.x;
            tile[(r  )*TSTR + col + 1] = acc[mt][nt][1] + bv.y;
            tile[(r+8)*TSTR + col]     = acc[mt][nt][2] + bv.x;
            tile[(r+8)*TSTR + col + 1] = acc[mt][nt][3] + bv.y;
        }
    }
    __syncthreads();

    const int bb    = bm >> 11;
    const int sbase = bm & 2047;

    if (bn < DMODEL) {
        const int h = bn >> 7;
        __half* dst = Qo + ((size_t)(bb*NHEADS + h))*SEQ*HDIM;
        const float scale = 0.08838834764831845f;
        for (int r = wid; r < 128; r += 8) {
            int s = sbase + r;
            int pos = seq_pos[bb*SEQ + s];
            __half* d = dst + (size_t)s*HDIM;
            #pragma unroll
            for (int ii = 0; ii < 2; ii++) {
                int i = lane + ii*32;
                float2 sc = rope[pos*64 + i];
                float x1 = tile[r*TSTR + i], x2 = tile[r*TSTR + i + 64];
                d[i]      = __float2half_rn((x1*sc.y - x2*sc.x) * scale);
                d[i + 64] = __float2half_rn((x2*sc.y + x1*sc.x) * scale);
            }
        }
    } else {
        const int off = bn - DMODEL;
        const int kv  = off >> 8;
        if (((off >> 7) & 1) == 0) {
            __half* dst = Ko + ((size_t)(bb*NKV + kv))*SEQ*HDIM;
            for (int r = wid; r < 128; r += 8) {
                int s = sbase + r;
                int pos = seq_pos[bb*SEQ + s];
                __half* d = dst + (size_t)s*HDIM;
                #pragma unroll
                for (int ii = 0; ii < 2; ii++) {
                    int i = lane + ii*32;
                    float2 sc = rope[pos*64 + i];
                    float x1 = tile[r*TSTR + i], x2 = tile[r*TSTR + i + 64];
                    d[i]      = __float2half_rn(x1*sc.y - x2*sc.x);
                    d[i + 64] = __float2half_rn(x2*sc.y + x1*sc.x);
                }
            }
        } else {
            __half* dst = Vt + ((size_t)(bb*NKV + kv))*HDIM*SEQ;
            #pragma unroll
            for (int ci = 0; ci < 16; ci++) {
                int c = wid*16 + ci;
                __half* dc = dst + (size_t)c*SEQ + sbase;
                #pragma unroll
                for (int rr = 0; rr < 4; rr++) {
                    int r = lane + rr*32;
                    dc[r] = __float2half_rn(tile[r*TSTR + c]);
                }
            }
        }
    }
}

// ---------------------------------------------------------------------------
// O-projection GEMM
// ---------------------------------------------------------------------------
__global__ __launch_bounds__(256, 2) void gemm_f16(
    const __half* __restrict__ A, const __half* __restrict__ B,
    const float* __restrict__ bias, float* __restrict__ C,
    int M, int N, int K)
{
    extern __shared__ __half sh[];
    const int tid  = threadIdx.x;
    const int lane = tid & 31, wid = tid >> 5;
    const int wr   = wid >> 2, wc = wid & 3;
    const int gr   = lane >> 2, qd = lane & 3;
    const int bm   = blockIdx.y*128, bn = blockIdx.x*128;

    float acc[4][4][4];
    #pragma unroll
    for (int i = 0; i < 4; i++)
        #pragma unroll
        for (int j = 0; j < 4; j++)
            #pragma unroll
            for (int r = 0; r < 4; r++) acc[i][j][r] = 0.f;

    GEMM_MAINLOOP()

    #pragma unroll
    for (int nt = 0; nt < 4; nt++) {
        int col = bn + wc*32 + nt*8 + 2*qd;
        float2 bv = *(const float2*)(bias + col);
        #pragma unroll
        for (int mt = 0; mt < 4; mt++) {
            int row = bm + wr*64 + mt*16 + gr;
            *(float2*)(C + (size_t)row*N + col) =
                make_float2(acc[mt][nt][0] + bv.x, acc[mt][nt][1] + bv.y);
            *(float2*)(C + (size_t)(row + 8)*N + col) =
                make_float2(acc[mt][nt][2] + bv.x, acc[mt][nt][3] + bv.y);
        }
    }
}

// ---------------------------------------------------------------------------
// Flash attention: 128 thr = 4 warps, warp owns 16 rows; Q/P in regs;
// K/V fragment loads via ldmatrix.
// ---------------------------------------------------------------------------
#define QS 136
#define VS 72
#define SMH_K0  0
#define SMH_K1  (64*QS)
#define SMH_V0  (2*64*QS)
#define SMH_V1  (2*64*QS + 128*VS)
#define FLASH_SMEM ((2*64*QS + 2*128*VS)*2)   // 71680 B

__global__ __launch_bounds__(128, 3) void flash_f16(
    const __half* __restrict__ Q, const __half* __restrict__ Kg,
    const __half* __restrict__ Vtg, __half* __restrict__ X)
{
    extern __shared__ __half smh[];

    const int qt  = 31 - blockIdx.x;
    const int h   = blockIdx.y;
    const int b   = blockIdx.z;
    const int kvh = h >> 2;
    const int q0  = qt * 64;

    const int tid  = threadIdx.x;
    const int lane = tid & 31, wid = tid >> 5;
    const int gr   = lane >> 2, qd = lane & 3;
    const int r0   = wid*16 + gr, r1 = r0 + 8;

    const __half* qb  = Q   + ((size_t)(b*NHEADS + h)*SEQ + q0)*HDIM;
    const __half* kb  = Kg  + (size_t)(b*NKV + kvh)*SEQ*HDIM;
    const __half* vtb = Vtg + (size_t)(b*NKV + kvh)*HDIM*SEQ;

    // ldmatrix lane offsets (B-fragment pattern: row n, col k)
    const uint32_t smb = (uint32_t)__cvta_generic_to_shared(smh);
    const int rowF = (lane & 7) + ((lane >> 4) << 3);
    const int colF = ((lane >> 3) & 1)*8;

    uint32_t qa[8][4];
    #pragma unroll
    for (int ks = 0; ks < 8; ks++) {
        qa[ks][0] = *(const uint32_t*)(qb + (size_t)r0*HDIM + ks*16     + 2*qd);
        qa[ks][1] = *(const uint32_t*)(qb + (size_t)r1*HDIM + ks*16     + 2*qd);
        qa[ks][2] = *(const uint32_t*)(qb + (size_t)r0*HDIM + ks*16 + 8 + 2*qd);
        qa[ks][3] = *(const uint32_t*)(qb + (size_t)r1*HDIM + ks*16 + 8 + 2*qd);
    }

    auto load_kv = [&](int buf, int kt) {
        __half* Ks = smh + (buf ? SMH_K1 : SMH_K0);
        __half* Vs = smh + (buf ? SMH_V1 : SMH_V0);
        const __half* kp = kb + (size_t)kt*64*HDIM;
        #pragma unroll
        for (int i = 0; i < 8; i++) {
            int slot = tid + i*128;
            int r = slot >> 4, c8 = (slot & 15)*8;
            cpa16(Ks + r*QS + c8, kp + r*HDIM + c8);
        }
        #pragma unroll
        for (int i = 0; i < 8; i++) {
            int slot = tid + i*128;
            int d = slot >> 3, c8 = (slot & 7)*8;
            cpa16(Vs + d*VS + c8, vtb + (size_t)d*SEQ + kt*64 + c8);
        }
        cp_commit();
    };

    load_kv(0, 0);

    float o[16][4];
    #pragma unroll
    for (int i = 0; i < 16; i++)
        #pragma unroll
        for (int j = 0; j < 4; j++) o[i][j] = 0.f;
    float m0 = -INFINITY, m1 = -INFINITY, l0 = 0.f, l1 = 0.f;

    for (int kt = 0; kt <= qt; kt++) {
        const int buf = kt & 1;
        __syncthreads();
        if (kt < qt) { load_kv(buf ^ 1, kt + 1); cp_wait1(); }
        else         { cp_wait0(); }
        __syncthreads();

        const uint32_t kBase = smb + ((buf ? SMH_K1 : SMH_K0) + rowF*QS + colF)*2;
        const uint32_t vBase = smb + ((buf ? SMH_V1 : SMH_V0) + rowF*VS + colF)*2;

        // ---- S = Q K^T : per ks, 4 ldsm.x4 cover nt=0..7 ----
        float s[8][4];
        #pragma unroll
        for (int nt = 0; nt < 8; nt++)
            #pragma unroll
            for (int j = 0; j < 4; j++) s[nt][j] = 0.f;

        #pragma unroll
        for (int ks = 0; ks < 8; ks++) {
            #pragma unroll
            for (int p = 0; p < 4; p++) {
                uint32_t bf[4];
                ldsm_x4(bf, kBase + (p*16*QS + ks*16)*2);
                mma_f16(s[2*p],     qa[ks], bf);
                mma_f16(s[2*p + 1], qa[ks], bf + 2);
            }
        }

        if (kt == qt) {
            #pragma unroll
            for (int nt = 0; nt < 8; nt++) {
                int cg = kt*64 + nt*8 + 2*qd;
                if (cg     > q0 + r0) s[nt][0] = -1e30f;
                if (cg + 1 > q0 + r0) s[nt][1] = -1e30f;
                if (cg     > q0 + r1) s[nt][2] = -1e30f;
                if (cg + 1 > q0 + r1) s[nt][3] = -1e30f;
            }
        }

        float mx0 = -INFINITY, mx1 = -INFINITY;
        #pragma unroll
        for (int nt = 0; nt < 8; nt++) {
            mx0 = fmaxf(mx0, fmaxf(s[nt][0], s[nt][1]));
            mx1 = fmaxf(mx1, fmaxf(s[nt][2], s[nt][3]));
        }
        mx0 = fmaxf(mx0, __shfl_xor_sync(0xffffffffu, mx0, 1));
        mx0 = fmaxf(mx0, __shfl_xor_sync(0xffffffffu, mx0, 2));
        mx1 = fmaxf(mx1, __shfl_xor_sync(0xffffffffu, mx1, 1));
        mx1 = fmaxf(mx1, __shfl_xor_sync(0xffffffffu, mx1, 2));
        float nm0 = fmaxf(m0, mx0), nm1 = fmaxf(m1, mx1);
        float corr0 = __expf(m0 - nm0), corr1 = __expf(m1 - nm1);

        uint32_t ph[8], pl[8];
        float sum0 = 0.f, sum1 = 0.f;
        #pragma unroll
        for (int nt = 0; nt < 8; nt++) {
            float p00 = __expf(s[nt][0] - nm0);
            float p01 = __expf(s[nt][1] - nm0);
            float p10 = __expf(s[nt][2] - nm1);
            float p11 = __expf(s[nt][3] - nm1);
            sum0 += p00 + p01; sum1 += p10 + p11;
            ph[nt] = packh2(p00, p01);
            pl[nt] = packh2(p10, p11);
        }
        sum0 += __shfl_xor_sync(0xffffffffu, sum0, 1);
        sum0 += __shfl_xor_sync(0xffffffffu, sum0, 2);
        sum1 += __shfl_xor_sync(0xffffffffu, sum1, 1);
        sum1 += __shfl_xor_sync(0xffffffffu, sum1, 2);
        l0 = l0*corr0 + sum0;
        l1 = l1*corr1 + sum1;
        m0 = nm0; m1 = nm1;

        #pragma unroll
        for (int nt = 0; nt < 16; nt++) {
            o[nt][0] *= corr0; o[nt][1] *= corr0;
            o[nt][2] *= corr1; o[nt][3] *= corr1;
        }

        // ---- O += P V : per k-step, 8 ldsm.x4 cover nt=0..15 ----
        #pragma unroll
        for (int t = 0; t < 4; t++) {
            uint32_t a[4] = { ph[2*t], pl[2*t], ph[2*t + 1], pl[2*t + 1] };
            #pragma unroll
            for (int p = 0; p < 8; p++) {
                uint32_t bf[4];
                ldsm_x4(bf, vBase + (p*16*VS + t*16)*2);
                mma_f16(o[2*p],     a, bf);
                mma_f16(o[2*p + 1], a, bf + 2);
            }
        }
    }

    float inv0 = 1.f / l0, inv1 = 1.f / l1;
    size_t rb0 = ((size_t)(b*SEQ + q0 + r0))*DMODEL + h*HDIM;
    size_t rb1 = ((size_t)(b*SEQ + q0 + r1))*DMODEL + h*HDIM;
    #pragma unroll
    for (int nt = 0; nt < 16; nt++) {
        int cc = nt*8 + 2*qd;
        *(__half2*)(X + rb0 + cc) = __floats2half2_rn(o[nt][0]*inv0, o[nt][1]*inv0);
        *(__half2*)(X + rb1 + cc) = __floats2half2_rn(o[nt][2]*inv1, o[nt][3]*inv1);
    }
}

// ---------------------------------------------------------------------------
// Launch
// ---------------------------------------------------------------------------
extern "C" void kernel_launch(void* const* d_in, const int* in_sizes, int n_in,
                              void* d_out, int out_size)
{
    const float* inputs  = (const float*)d_in[0];
    const int*   seq_pos = (const int*)  d_in[1];
    const float* wq      = (const float*)d_in[2];
    const float* bq      = (const float*)d_in[3];
    const float* wkv     = (const float*)d_in[4];
    const float* bkv     = (const float*)d_in[5];
    const float* wo      = (const float*)d_in[6];
    const float* bo      = (const float*)d_in[7];
    float* out = (float*)d_out;

    __half *in_h, *wqkv_h, *wo_h, *x_h, *q, *k, *vt;
    float2* rope;
    cudaGetSymbolAddress((void**)&in_h,   g_in_h);
    cudaGetSymbolAddress((void**)&wqkv_h, g_wqkv_h);
    cudaGetSymbolAddress((void**)&wo_h,   g_wo_h);
    cudaGetSymbolAddress((void**)&x_h,    g_x_h);
    cudaGetSymbolAddress((void**)&q,      g_q);
    cudaGetSymbolAddress((void**)&k,      g_k);
    cudaGetSymbolAddress((void**)&vt,     g_vt);
    cudaGetSymbolAddress((void**)&rope,   g_rope);

    const int GEMM_SMEM = 2*HBUF*2;     // 73728 B
    cudaFuncSetAttribute(gemm_qkv,
                         cudaFuncAttributeMaxDynamicSharedMemorySize, GEMM_SMEM);
    cudaFuncSetAttribute(gemm_f16,
                         cudaFuncAttributeMaxDynamicSharedMemorySize, GEMM_SMEM);
    cudaFuncSetAttribute(flash_f16,
                         cudaFuncAttributeMaxDynamicSharedMemorySize, FLASH_SMEM);

    // 0) merged staging
    staging<<<STG_TOT, 256>>>((const float4*)inputs, wq, wkv, wo,
                              (__half2*)in_h, wqkv_h, wo_h, rope);

    // 1) fused QKV projection + rope + V transpose
    gemm_qkv<<<dim3(NQKV/128, M_TOK/128), 256, GEMM_SMEM>>>(
        in_h, wqkv_h, bq, bkv, seq_pos, rope, q, k, vt);

    // 2) flash attention
    flash_f16<<<dim3(SEQ/64, NHEADS, BATCH), 128, FLASH_SMEM>>>(q, k, vt, x_h);

    // 3) output projection
    gemm_f16<<<dim3(DMODEL/128, M_TOK/128), 256, GEMM_SMEM>>>(
        x_h, wo_h, bo, out, M_TOK, DMODEL, DMODEL);
}